// round 11
// baseline (speedup 1.0000x reference)
#include <cuda_runtime.h>
#include <cuda_fp16.h>
#include <math.h>
#include <stdint.h>

// ================= scratch (no allocations allowed) =================
#define MAX_ATOMS 100000
__device__ float g_b2a[MAX_ATOMS * 32];
__device__ float g_cnt[MAX_ATOMS];
__device__ float g_bsum[32];
__device__ float g_asum[32];

// pre-transposed fp16 weight images Wt[n][k], padded k-stride
__device__ __align__(16) __half g_we[15616];  // W1@0 W2@8704 W3@13312 (halves)
__device__ __align__(16) __half g_wv[13568];  // V1@0 V2@6656 V3@11264

__device__ __forceinline__ float selu_f(float x) {
    const float lam = 1.0507009873554805f;
    const float la  = 1.7580993408473766f;
    float e = __expf(x);
    return x > 0.f ? lam * x : fmaf(la, e, -la);
}

// fp32 pair -> fp16x2 hi word + fp16x2 residual word (packed cvt)
__device__ __forceinline__ void split_pair(float v0, float v1, uint32_t& hw, uint32_t& lw) {
    __half2 hp = __floats2half2_rn(v0, v1);
    float2 hf = __half22float2(hp);
    __half2 lp = __floats2half2_rn(v0 - hf.x, v1 - hf.y);
    hw = *(uint32_t*)&hp;
    lw = *(uint32_t*)&lp;
}

__device__ __forceinline__ uint32_t smem_u32(const void* p) {
    uint32_t a;
    asm("{ .reg .u64 t; cvta.to.shared.u64 t, %1; cvt.u32.u64 %0, t; }" : "=r"(a) : "l"(p));
    return a;
}

// ---- baseline-ISA ops (valid on plain sm_100) ----
__device__ __forceinline__ void ldmx4(uint32_t r[4], uint32_t addr) {
    asm volatile("ldmatrix.sync.aligned.m8n8.x4.shared.b16 {%0,%1,%2,%3}, [%4];"
        : "=r"(r[0]), "=r"(r[1]), "=r"(r[2]), "=r"(r[3]) : "r"(addr));
}
__device__ __forceinline__ void mma_f16(float c[4], const uint32_t a[4], uint32_t b0, uint32_t b1) {
    asm("mma.sync.aligned.m16n8k16.row.col.f32.f16.f16.f32 "
        "{%0,%1,%2,%3}, {%4,%5,%6,%7}, {%8,%9}, {%0,%1,%2,%3};"
        : "+f"(c[0]), "+f"(c[1]), "+f"(c[2]), "+f"(c[3])
        : "r"(a[0]), "r"(a[1]), "r"(a[2]), "r"(a[3]), "r"(b0), "r"(b1));
}
__device__ __forceinline__ void cp16(uint32_t dst, const void* src) {
    asm volatile("cp.async.ca.shared.global [%0], [%1], 16;" :: "r"(dst), "l"(src));
}
#define CP_COMMIT() asm volatile("cp.async.commit_group;" ::: "memory")
#define CP_WAIT0()  asm volatile("cp.async.wait_group 0;" ::: "memory")
// pair-scoped barrier: 2 warps (64 threads), ids 1..4
#define PAIR_BAR(wm) asm volatile("bar.sync %0, 64;" :: "r"((wm) + 1) : "memory")

// dense layer: acc[NTW][4] += A(16 rows x K) @ Wt^T  (fp16 2-pass)
template <int KS, int NTW>
__device__ __forceinline__ void mlp_layer(
    uint32_t xh_addr, uint32_t xl_addr,
    uint32_t b_addr, uint32_t sbwB,
    float acc[NTW][4])
{
#pragma unroll
    for (int j = 0; j < NTW; j++)
#pragma unroll
        for (int q = 0; q < 4; q++) acc[j][q] = 0.f;

#pragma unroll
    for (int k = 0; k < KS; k++) {
        uint32_t ah[4], al[4];
        ldmx4(ah, xh_addr);
        ldmx4(al, xl_addr);
        xh_addr += 32; xl_addr += 32;
#pragma unroll
        for (int p = 0; p < NTW / 2; p++) {
            uint32_t rw[4];
            ldmx4(rw, b_addr + p * 8 * sbwB * 2);
            mma_f16(acc[2 * p],     ah, rw[0], rw[1]);
            mma_f16(acc[2 * p + 1], ah, rw[2], rw[3]);
            mma_f16(acc[2 * p],     al, rw[0], rw[1]);
            mma_f16(acc[2 * p + 1], al, rw[2], rw[3]);
        }
        b_addr += 32;
    }
}

// epilogue: bias+selu -> split -> pair-LOCAL fp16 H images (rows 0..15, stride 36 words)
template <int NTW>
__device__ __forceinline__ void epi_to_h(
    float acc[NTW][4], const float* bias,
    uint32_t* Hh, uint32_t* Hl, int wn, int g, int t)
{
    const int r0 = g;  // local row within pair
#pragma unroll
    for (int j = 0; j < NTW; j++) {
        int col = wn * 32 + j * 8 + 2 * t;
        int cw  = wn * 16 + j * 4 + t;
        float b0 = bias[col], b1 = bias[col + 1];
        uint32_t hw, lw;
        split_pair(selu_f(acc[j][0] + b0), selu_f(acc[j][1] + b1), hw, lw);
        Hh[r0 * 36 + cw] = hw; Hl[r0 * 36 + cw] = lw;
        split_pair(selu_f(acc[j][2] + b0), selu_f(acc[j][3] + b1), hw, lw);
        Hh[(r0 + 8) * 36 + cw] = hw; Hl[(r0 + 8) * 36 + cw] = lw;
    }
}

// ================= zero scratch =================
__global__ void zero_kernel(int n_atoms)
{
    int i = blockIdx.x * blockDim.x + threadIdx.x;
    int stride = gridDim.x * blockDim.x;
    int nb = n_atoms * 32;
    for (int idx = i; idx < nb; idx += stride) g_b2a[idx] = 0.f;
    for (int idx = i; idx < n_atoms; idx += stride) g_cnt[idx] = 0.f;
    if (i < 32) { g_bsum[i] = 0.f; g_asum[i] = 0.f; }
}

// ================= weight transpose prep =================
__global__ void prep_kernel(
    const float* __restrict__ ew1, const float* __restrict__ ew2, const float* __restrict__ ew3,
    const float* __restrict__ vw1, const float* __restrict__ vw2, const float* __restrict__ vw3)
{
    int i = blockIdx.x * blockDim.x + threadIdx.x;
    if (i >= 29184) return;
    const float* src; __half* img;
    int stride, N, Ksrc, local;
    if (i < 8704)        { local = i;         stride = 136; N = 64; Ksrc = 128; src = ew1; img = g_we; }
    else if (i < 13312)  { local = i - 8704;  stride = 72;  N = 64; Ksrc = 64;  src = ew2; img = g_we + 8704; }
    else if (i < 15616)  { local = i - 13312; stride = 72;  N = 32; Ksrc = 64;  src = ew3; img = g_we + 13312; }
    else if (i < 22272)  { local = i - 15616; stride = 104; N = 64; Ksrc = 96;  src = vw1; img = g_wv; }
    else if (i < 26880)  { local = i - 22272; stride = 72;  N = 64; Ksrc = 64;  src = vw2; img = g_wv + 6656; }
    else                 { local = i - 26880; stride = 72;  N = 32; Ksrc = 64;  src = vw3; img = g_wv + 11264; }
    int n = local / stride, k = local % stride;
    float w = (k < Ksrc) ? src[k * N + n] : 0.f;
    img[local] = __float2half(w);
}

// ================= smem maps (bytes) =================
// bond: Xh 17408 + Xl 17408 (pair's H overlays its own 4352B X range); weights follow
#define B_BIAS   0
#define B_A1S    640
#define B_XB     1024
#define B_WB     35840
#define B_SMEM   67072
// atom: Xh 13312 + Xl 13312; weights follow
#define A_BIAS   0
#define A_XB     768
#define A_WB     27392
#define A_SMEM   54528

#define NT 256
#define TMROWS 64

// ================= phi_e over bonds =================
__global__ void __launch_bounds__(NT, 3) bond_kernel(
    const float* __restrict__ bonds, const int* __restrict__ ba1,
    const int* __restrict__ ba2, const float* __restrict__ atoms,
    const float* __restrict__ state,
    const float* __restrict__ eb1, const float* __restrict__ eb2,
    const float* __restrict__ eb3,
    float* __restrict__ out_bonds, int n_bonds)
{
    extern __shared__ char smem[];
    const uint32_t sb = smem_u32(smem);
    const int tid  = threadIdx.x;
    const int wid  = tid >> 5;
    const int lane = tid & 31;
    const int g = lane >> 2, t = lane & 3;
    const int wm = wid >> 1, wn = wid & 1;   // 4 pairs x 2 n-warps
    const int base = blockIdx.x * TMROWS;

    float* Bs  = (float*)(smem + B_BIAS);
    int*   A1s = (int*)(smem + B_A1S);
    uint32_t* Xh = (uint32_t*)(smem + B_XB);
    uint32_t* Xl = (uint32_t*)(smem + B_XB + 17408);
    // pair-local H (inside own X range)
    uint32_t* Hh = Xh + wm * 1088;
    uint32_t* Hl = Xl + wm * 1088;

    // weights -> smem (cp.async)
    for (int i = tid; i < 31232 / 16; i += NT)
        cp16(sb + B_WB + i * 16, (const char*)g_we + i * 16);
    CP_COMMIT();
    if (tid < 64) { Bs[tid] = eb1[tid]; Bs[64 + tid] = eb2[tid]; }
    else if (tid < 96) Bs[128 + tid - 64] = eb3[tid - 64];

    // ---- stage X: 64 rows x 4 quarters ----
    {
        const int m = tid >> 2, q = tid & 3;
        const int gid = base + m;
        const float* src;
        if (q == 0) {
            int a1 = ba1[gid];
            A1s[m] = a1;
            atomicAdd(&g_cnt[a1], 1.0f);
            src = atoms + (size_t)a1 * 32;
        } else if (q == 1) {
            src = atoms + (size_t)ba2[gid] * 32;
        } else if (q == 2) {
            src = bonds + (size_t)gid * 32;
        } else {
            src = state;
        }
        const int wbase = m * 68 + q * 16;
#pragma unroll
        for (int p = 0; p < 8; p++) {
            float4 v = *(const float4*)(src + 4 * p);
            uint32_t hw, lw;
            split_pair(v.x, v.y, hw, lw);
            Xh[wbase + 2 * p] = hw; Xl[wbase + 2 * p] = lw;
            split_pair(v.z, v.w, hw, lw);
            Xh[wbase + 2 * p + 1] = hw; Xl[wbase + 2 * p + 1] = lw;
        }
    }
    CP_WAIT0();
    __syncthreads();

    // lane-resolved fragment offsets
    const uint32_t a_loc = (uint32_t)(lane & 15);          // local row in pair
    const uint32_t a_kb  = (uint32_t)((lane >> 4) << 4);
    const uint32_t b_row = (uint32_t)(((lane >> 4) << 3) + (lane & 7));
    const uint32_t b_kb  = (uint32_t)(((lane >> 3) & 1) << 4);
    const uint32_t hb_h  = sb + B_XB + (uint32_t)wm * 4352;          // pair H hi base
    const uint32_t hb_l  = sb + B_XB + 17408 + (uint32_t)wm * 4352;  // pair H lo base

    // ---- layer 1: K=128 (X stride 272B), W1 stride 272B ----
    {
        float acc[4][4];
        uint32_t ao = ((uint32_t)(wm * 16) + a_loc) * 272 + a_kb;
        uint32_t bo = (wn * 32 + b_row) * 272 + b_kb;
        mlp_layer<8, 4>(sb + B_XB + ao, sb + B_XB + 17408 + ao,
                        sb + B_WB + bo, 272, acc);
        PAIR_BAR(wm);  // pair done reading its X rows
        epi_to_h<4>(acc, Bs, Hh, Hl, wn, g, t);
    }
    PAIR_BAR(wm);

    // ---- layer 2: K=64 (H stride 144B), W2 stride 144B ----
    {
        float acc[4][4];
        uint32_t ao = a_loc * 144 + a_kb;
        uint32_t bo = (wn * 32 + b_row) * 144 + b_kb;
        mlp_layer<4, 4>(hb_h + ao, hb_l + ao,
                        sb + B_WB + 17408 + bo, 144, acc);
        PAIR_BAR(wm);  // pair done reading H1
        epi_to_h<4>(acc, Bs + 64, Hh, Hl, wn, g, t);
    }
    PAIR_BAR(wm);

    // ---- layer 3: K=64, N=32 + register-direct epilogue ----
    {
        float acc[2][4];
        uint32_t ao = a_loc * 144 + a_kb;
        uint32_t bo = (wn * 16 + b_row) * 144 + b_kb;
        mlp_layer<4, 2>(hb_h + ao, hb_l + ao,
                        sb + B_WB + 26624 + bo, 144, acc);

        const int r0 = wm * 16 + g;             // block-local rows r0, r0+8
        const int a1a = A1s[r0], a1b = A1s[r0 + 8];
        float bp[4];
#pragma unroll
        for (int j = 0; j < 2; j++) {
            int col = wn * 16 + j * 8 + 2 * t;
            float b0 = Bs[128 + col], b1 = Bs[128 + col + 1];
            float v0 = selu_f(acc[j][0] + b0);
            float v1 = selu_f(acc[j][1] + b1);
            float v2 = selu_f(acc[j][2] + b0);
            float v3 = selu_f(acc[j][3] + b1);
            float2 s;
            s.x = v0; s.y = v1;
            *(float2*)&out_bonds[(size_t)(base + r0) * 32 + col] = s;
            s.x = v2; s.y = v3;
            *(float2*)&out_bonds[(size_t)(base + r0 + 8) * 32 + col] = s;
            atomicAdd(&g_b2a[(size_t)a1a * 32 + col],     v0);
            atomicAdd(&g_b2a[(size_t)a1a * 32 + col + 1], v1);
            atomicAdd(&g_b2a[(size_t)a1b * 32 + col],     v2);
            atomicAdd(&g_b2a[(size_t)a1b * 32 + col + 1], v3);
            bp[2 * j]     = v0 + v2;
            bp[2 * j + 1] = v1 + v3;
        }
        // shuffle-reduce partials over g (8 lanes)
#pragma unroll
        for (int mask = 4; mask <= 16; mask <<= 1)
#pragma unroll
            for (int q = 0; q < 4; q++)
                bp[q] += __shfl_xor_sync(0xffffffffu, bp[q], mask);
        if (g == 0) {
            int c0 = wn * 16 + 2 * t;
            atomicAdd(&g_bsum[c0],     bp[0]);
            atomicAdd(&g_bsum[c0 + 1], bp[1]);
            atomicAdd(&g_bsum[c0 + 8], bp[2]);
            atomicAdd(&g_bsum[c0 + 9], bp[3]);
        }
    }
}

// ================= phi_v over atoms =================
__global__ void __launch_bounds__(NT, 3) atom_kernel(
    const float* __restrict__ atoms, const float* __restrict__ state,
    const float* __restrict__ vb1, const float* __restrict__ vb2,
    const float* __restrict__ vb3,
    float* __restrict__ out_atoms, int n_atoms)
{
    extern __shared__ char smem[];
    const uint32_t sb = smem_u32(smem);
    const int tid  = threadIdx.x;
    const int wid  = tid >> 5;
    const int lane = tid & 31;
    const int g = lane >> 2, t = lane & 3;
    const int wm = wid >> 1, wn = wid & 1;
    const int base = blockIdx.x * TMROWS;

    float* Bs = (float*)(smem + A_BIAS);
    uint32_t* Xh = (uint32_t*)(smem + A_XB);
    uint32_t* Xl = (uint32_t*)(smem + A_XB + 13312);
    uint32_t* Hh = Xh + wm * 832;   // pair X range = 16*52 = 832 words
    uint32_t* Hl = Xl + wm * 832;

    for (int i = tid; i < 27136 / 16; i += NT)
        cp16(sb + A_WB + i * 16, (const char*)g_wv + i * 16);
    CP_COMMIT();
    if (tid < 64) { Bs[tid] = vb1[tid]; Bs[64 + tid] = vb2[tid]; }
    else if (tid < 96) Bs[128 + tid - 64] = vb3[tid - 64];

    // ---- stage X: 64 rows x 3 thirds (quarter 3 idle) ----
    {
        const int m = tid >> 2, q = tid & 3;
        if (q < 3) {
            const int gm = base + m;
            const int id = gm < n_atoms ? gm : n_atoms - 1;
            const int wbase = m * 52 + q * 16;
            if (q == 0) {
                float inv = 1.0f / g_cnt[id];
#pragma unroll
                for (int p = 0; p < 8; p++) {
                    float4 v = *(const float4*)&g_b2a[(size_t)id * 32 + 4 * p];
                    uint32_t hw, lw;
                    split_pair(v.x * inv, v.y * inv, hw, lw);
                    Xh[wbase + 2 * p] = hw; Xl[wbase + 2 * p] = lw;
                    split_pair(v.z * inv, v.w * inv, hw, lw);
                    Xh[wbase + 2 * p + 1] = hw; Xl[wbase + 2 * p + 1] = lw;
                }
            } else {
                const float* src = (q == 1) ? atoms + (size_t)id * 32 : state;
#pragma unroll
                for (int p = 0; p < 8; p++) {
                    float4 v = *(const float4*)(src + 4 * p);
                    uint32_t hw, lw;
                    split_pair(v.x, v.y, hw, lw);
                    Xh[wbase + 2 * p] = hw; Xl[wbase + 2 * p] = lw;
                    split_pair(v.z, v.w, hw, lw);
                    Xh[wbase + 2 * p + 1] = hw; Xl[wbase + 2 * p + 1] = lw;
                }
            }
        }
    }
    CP_WAIT0();
    __syncthreads();

    const uint32_t a_loc = (uint32_t)(lane & 15);
    const uint32_t a_kb  = (uint32_t)((lane >> 4) << 4);
    const uint32_t b_row = (uint32_t)(((lane >> 4) << 3) + (lane & 7));
    const uint32_t b_kb  = (uint32_t)(((lane >> 3) & 1) << 4);
    const uint32_t hb_h  = sb + A_XB + (uint32_t)wm * 3328;
    const uint32_t hb_l  = sb + A_XB + 13312 + (uint32_t)wm * 3328;

    // ---- layer 1: K=96 (X stride 208B) ----
    {
        float acc[4][4];
        uint32_t ao = ((uint32_t)(wm * 16) + a_loc) * 208 + a_kb;
        uint32_t bo = (wn * 32 + b_row) * 208 + b_kb;
        mlp_layer<6, 4>(sb + A_XB + ao, sb + A_XB + 13312 + ao,
                        sb + A_WB + bo, 208, acc);
        PAIR_BAR(wm);
        epi_to_h<4>(acc, Bs, Hh, Hl, wn, g, t);
    }
    PAIR_BAR(wm);

    // ---- layer 2 ----
    {
        float acc[4][4];
        uint32_t ao = a_loc * 144 + a_kb;
        uint32_t bo = (wn * 32 + b_row) * 144 + b_kb;
        mlp_layer<4, 4>(hb_h + ao, hb_l + ao,
                        sb + A_WB + 13312 + bo, 144, acc);
        PAIR_BAR(wm);
        epi_to_h<4>(acc, Bs + 64, Hh, Hl, wn, g, t);
    }
    PAIR_BAR(wm);

    // ---- layer 3 + register-direct epilogue ----
    {
        float acc[2][4];
        uint32_t ao = a_loc * 144 + a_kb;
        uint32_t bo = (wn * 16 + b_row) * 144 + b_kb;
        mlp_layer<4, 2>(hb_h + ao, hb_l + ao,
                        sb + A_WB + 22528 + bo, 144, acc);

        const int r0 = wm * 16 + g;
        const bool v0ok = (base + r0) < n_atoms;
        const bool v1ok = (base + r0 + 8) < n_atoms;
        float ap[4];
#pragma unroll
        for (int j = 0; j < 2; j++) {
            int col = wn * 16 + j * 8 + 2 * t;
            float b0 = Bs[128 + col], b1 = Bs[128 + col + 1];
            float v0 = selu_f(acc[j][0] + b0);
            float v1 = selu_f(acc[j][1] + b1);
            float v2 = selu_f(acc[j][2] + b0);
            float v3 = selu_f(acc[j][3] + b1);
            float2 s;
            if (v0ok) {
                s.x = v0; s.y = v1;
                *(float2*)&out_atoms[(size_t)(base + r0) * 32 + col] = s;
            }
            if (v1ok) {
                s.x = v2; s.y = v3;
                *(float2*)&out_atoms[(size_t)(base + r0 + 8) * 32 + col] = s;
            }
            ap[2 * j]     = (v0ok ? v0 : 0.f) + (v1ok ? v2 : 0.f);
            ap[2 * j + 1] = (v0ok ? v1 : 0.f) + (v1ok ? v3 : 0.f);
        }
#pragma unroll
        for (int mask = 4; mask <= 16; mask <<= 1)
#pragma unroll
            for (int q = 0; q < 4; q++)
                ap[q] += __shfl_xor_sync(0xffffffffu, ap[q], mask);
        if (g == 0) {
            int c0 = wn * 16 + 2 * t;
            atomicAdd(&g_asum[c0],     ap[0]);
            atomicAdd(&g_asum[c0 + 1], ap[1]);
            atomicAdd(&g_asum[c0 + 8], ap[2]);
            atomicAdd(&g_asum[c0 + 9], ap[3]);
        }
    }
}

// ================= phi_u =================
__global__ void state_kernel(
    const float* __restrict__ state,
    const float* __restrict__ uw1, const float* __restrict__ ub1,
    const float* __restrict__ uw2, const float* __restrict__ ub2,
    const float* __restrict__ uw3, const float* __restrict__ ub3,
    float* __restrict__ out_state, int n_bonds, int n_atoms)
{
    __shared__ float x[96], h1[64], h2[64];
    int tid = threadIdx.x;  // 64 threads
    if (tid < 32) {
        x[tid]      = g_bsum[tid] / (float)n_bonds;
        x[32 + tid] = g_asum[tid] / (float)n_atoms;
        x[64 + tid] = state[tid];
    }
    __syncthreads();
    {
        float a = ub1[tid];
        for (int k = 0; k < 96; k++) a = fmaf(x[k], uw1[k * 64 + tid], a);
        h1[tid] = selu_f(a);
    }
    __syncthreads();
    {
        float a = ub2[tid];
        for (int k = 0; k < 64; k++) a = fmaf(h1[k], uw2[k * 64 + tid], a);
        h2[tid] = selu_f(a);
    }
    __syncthreads();
    if (tid < 32) {
        float a = ub3[tid];
        for (int k = 0; k < 64; k++) a = fmaf(h2[k], uw3[k * 32 + tid], a);
        out_state[tid] = selu_f(a);
    }
}

// ================= launch =================
extern "C" void kernel_launch(void* const* d_in, const int* in_sizes, int n_in,
                              void* d_out, int out_size)
{
    const float* bonds = (const float*)d_in[0];
    const int*   ba1   = (const int*)d_in[1];
    const int*   ba2   = (const int*)d_in[2];
    const float* atoms = (const float*)d_in[3];
    const float* state = (const float*)d_in[4];
    const float* ew1 = (const float*)d_in[5];
    const float* eb1 = (const float*)d_in[6];
    const float* ew2 = (const float*)d_in[7];
    const float* eb2 = (const float*)d_in[8];
    const float* ew3 = (const float*)d_in[9];
    const float* eb3 = (const float*)d_in[10];
    const float* vw1 = (const float*)d_in[11];
    const float* vb1 = (const float*)d_in[12];
    const float* vw2 = (const float*)d_in[13];
    const float* vb2 = (const float*)d_in[14];
    const float* vw3 = (const float*)d_in[15];
    const float* vb3 = (const float*)d_in[16];
    const float* uw1 = (const float*)d_in[17];
    const float* ub1 = (const float*)d_in[18];
    const float* uw2 = (const float*)d_in[19];
    const float* ub2 = (const float*)d_in[20];
    const float* uw3 = (const float*)d_in[21];
    const float* ub3 = (const float*)d_in[22];

    const int n_bonds = in_sizes[1];
    const int n_atoms = in_sizes[3] / 32;

    float* out       = (float*)d_out;
    float* out_bonds = out;
    float* out_atoms = out + (size_t)n_bonds * 32;
    float* out_state = out_atoms + (size_t)n_atoms * 32;

    cudaFuncSetAttribute(bond_kernel, cudaFuncAttributeMaxDynamicSharedMemorySize, B_SMEM);
    cudaFuncSetAttribute(atom_kernel, cudaFuncAttributeMaxDynamicSharedMemorySize, A_SMEM);

    zero_kernel<<<256, 256>>>(n_atoms);
    prep_kernel<<<(29184 + 255) / 256, 256>>>(ew1, ew2, ew3, vw1, vw2, vw3);

    int bond_blocks = n_bonds / TMROWS;
    bond_kernel<<<bond_blocks, NT, B_SMEM>>>(
        bonds, ba1, ba2, atoms, state, eb1, eb2, eb3, out_bonds, n_bonds);

    int atom_blocks = (n_atoms + TMROWS - 1) / TMROWS;
    atom_kernel<<<atom_blocks, NT, A_SMEM>>>(
        atoms, state, vb1, vb2, vb3, out_atoms, n_atoms);

    state_kernel<<<1, 64>>>(state, uw1, ub1, uw2, ub2, uw3, ub3,
                            out_state, n_bonds, n_atoms);
}

// round 12
// speedup vs baseline: 1.1418x; 1.1418x over previous
#include <cuda_runtime.h>
#include <cuda_fp16.h>
#include <math.h>
#include <stdint.h>

// ================= scratch (no allocations allowed) =================
#define MAX_ATOMS 100000
__device__ float g_b2a[MAX_ATOMS * 32];
__device__ float g_cnt[MAX_ATOMS];
__device__ float g_bsum[32];
__device__ float g_asum[32];

// pre-transposed fp16 weight images Wt[n][k], padded k-stride
__device__ __align__(16) __half g_we[15616];  // W1@0 W2@8704 W3@13312 (halves)
__device__ __align__(16) __half g_wv[13568];  // V1@0 V2@6656 V3@11264

__device__ __forceinline__ float selu_f(float x) {
    const float lam = 1.0507009873554805f;
    const float la  = 1.7580993408473766f;
    float e = __expf(x);
    return x > 0.f ? lam * x : fmaf(la, e, -la);
}

// fp32 pair -> fp16x2 hi word + fp16x2 residual word (packed cvt)
__device__ __forceinline__ void split_pair(float v0, float v1, uint32_t& hw, uint32_t& lw) {
    __half2 hp = __floats2half2_rn(v0, v1);
    float2 hf = __half22float2(hp);
    __half2 lp = __floats2half2_rn(v0 - hf.x, v1 - hf.y);
    hw = *(uint32_t*)&hp;
    lw = *(uint32_t*)&lp;
}

__device__ __forceinline__ uint32_t smem_u32(const void* p) {
    uint32_t a;
    asm("{ .reg .u64 t; cvta.to.shared.u64 t, %1; cvt.u32.u64 %0, t; }" : "=r"(a) : "l"(p));
    return a;
}

// ---- baseline-ISA ops (valid on plain sm_100) ----
__device__ __forceinline__ void ldmx4(uint32_t r[4], uint32_t addr) {
    asm volatile("ldmatrix.sync.aligned.m8n8.x4.shared.b16 {%0,%1,%2,%3}, [%4];"
        : "=r"(r[0]), "=r"(r[1]), "=r"(r[2]), "=r"(r[3]) : "r"(addr));
}
__device__ __forceinline__ void mma_f16(float c[4], const uint32_t a[4], uint32_t b0, uint32_t b1) {
    asm("mma.sync.aligned.m16n8k16.row.col.f32.f16.f16.f32 "
        "{%0,%1,%2,%3}, {%4,%5,%6,%7}, {%8,%9}, {%0,%1,%2,%3};"
        : "+f"(c[0]), "+f"(c[1]), "+f"(c[2]), "+f"(c[3])
        : "r"(a[0]), "r"(a[1]), "r"(a[2]), "r"(a[3]), "r"(b0), "r"(b1));
}
__device__ __forceinline__ void cp16(uint32_t dst, const void* src) {
    asm volatile("cp.async.ca.shared.global [%0], [%1], 16;" :: "r"(dst), "l"(src));
}
#define CP_COMMIT() asm volatile("cp.async.commit_group;" ::: "memory")
#define CP_WAIT0()  asm volatile("cp.async.wait_group 0;" ::: "memory")
// pair-scoped barrier: 2 warps (64 threads), ids 1..4
#define PAIR_BAR(wm) asm volatile("bar.sync %0, 64;" :: "r"((wm) + 1) : "memory")

// dense layer: acc[NTW][4] += A(16 rows x K) @ Wt^T  (fp16 2-pass)
template <int KS, int NTW>
__device__ __forceinline__ void mlp_layer(
    uint32_t xh_addr, uint32_t xl_addr,
    uint32_t b_addr, uint32_t sbwB,
    float acc[NTW][4])
{
#pragma unroll
    for (int j = 0; j < NTW; j++)
#pragma unroll
        for (int q = 0; q < 4; q++) acc[j][q] = 0.f;

#pragma unroll
    for (int k = 0; k < KS; k++) {
        uint32_t ah[4], al[4];
        ldmx4(ah, xh_addr);
        ldmx4(al, xl_addr);
        xh_addr += 32; xl_addr += 32;
#pragma unroll
        for (int p = 0; p < NTW / 2; p++) {
            uint32_t rw[4];
            ldmx4(rw, b_addr + p * 8 * sbwB * 2);
            mma_f16(acc[2 * p],     ah, rw[0], rw[1]);
            mma_f16(acc[2 * p + 1], ah, rw[2], rw[3]);
            mma_f16(acc[2 * p],     al, rw[0], rw[1]);
            mma_f16(acc[2 * p + 1], al, rw[2], rw[3]);
        }
        b_addr += 32;
    }
}

// epilogue: bias+selu -> split -> pair-LOCAL fp16 H images (rows 0..15, stride 36 words)
template <int NTW>
__device__ __forceinline__ void epi_to_h(
    float acc[NTW][4], const float* bias,
    uint32_t* Hh, uint32_t* Hl, int wn, int g, int t)
{
    const int r0 = g;  // local row within pair
#pragma unroll
    for (int j = 0; j < NTW; j++) {
        int col = wn * 32 + j * 8 + 2 * t;
        int cw  = wn * 16 + j * 4 + t;
        float b0 = bias[col], b1 = bias[col + 1];
        uint32_t hw, lw;
        split_pair(selu_f(acc[j][0] + b0), selu_f(acc[j][1] + b1), hw, lw);
        Hh[r0 * 36 + cw] = hw; Hl[r0 * 36 + cw] = lw;
        split_pair(selu_f(acc[j][2] + b0), selu_f(acc[j][3] + b1), hw, lw);
        Hh[(r0 + 8) * 36 + cw] = hw; Hl[(r0 + 8) * 36 + cw] = lw;
    }
}

// ================= zero scratch =================
__global__ void zero_kernel(int n_atoms)
{
    int i = blockIdx.x * blockDim.x + threadIdx.x;
    int stride = gridDim.x * blockDim.x;
    int nb = n_atoms * 32;
    for (int idx = i; idx < nb; idx += stride) g_b2a[idx] = 0.f;
    for (int idx = i; idx < n_atoms; idx += stride) g_cnt[idx] = 0.f;
    if (i < 32) { g_bsum[i] = 0.f; g_asum[i] = 0.f; }
}

// ================= weight transpose prep =================
__global__ void prep_kernel(
    const float* __restrict__ ew1, const float* __restrict__ ew2, const float* __restrict__ ew3,
    const float* __restrict__ vw1, const float* __restrict__ vw2, const float* __restrict__ vw3)
{
    int i = blockIdx.x * blockDim.x + threadIdx.x;
    if (i >= 29184) return;
    const float* src; __half* img;
    int stride, N, Ksrc, local;
    if (i < 8704)        { local = i;         stride = 136; N = 64; Ksrc = 128; src = ew1; img = g_we; }
    else if (i < 13312)  { local = i - 8704;  stride = 72;  N = 64; Ksrc = 64;  src = ew2; img = g_we + 8704; }
    else if (i < 15616)  { local = i - 13312; stride = 72;  N = 32; Ksrc = 64;  src = ew3; img = g_we + 13312; }
    else if (i < 22272)  { local = i - 15616; stride = 104; N = 64; Ksrc = 96;  src = vw1; img = g_wv; }
    else if (i < 26880)  { local = i - 22272; stride = 72;  N = 64; Ksrc = 64;  src = vw2; img = g_wv + 6656; }
    else                 { local = i - 26880; stride = 72;  N = 32; Ksrc = 64;  src = vw3; img = g_wv + 11264; }
    int n = local / stride, k = local % stride;
    float w = (k < Ksrc) ? src[k * N + n] : 0.f;
    img[local] = __float2half(w);
}

// ================= smem maps (bytes) =================
// bond: Xh 17408 + Xl 17408 (pair's H overlays its own 4352B X range)
// H3 @ B_XB+34816 (9216); weights @ B_XB+44032 (31232)
#define B_BIAS   0
#define B_A1S    640
#define B_XB     1024
#define B_WB     45056
#define B_SMEM   76288
// atom: Xh 13312 + Xl 13312; H3 @ A_XB+26624; weights @ 36608
#define A_BIAS   0
#define A_XB     768
#define A_WB     36608
#define A_SMEM   63744

#define NT 256
#define TMROWS 64

// ================= phi_e over bonds =================
__global__ void __launch_bounds__(NT, 3) bond_kernel(
    const float* __restrict__ bonds, const int* __restrict__ ba1,
    const int* __restrict__ ba2, const float* __restrict__ atoms,
    const float* __restrict__ state,
    const float* __restrict__ eb1, const float* __restrict__ eb2,
    const float* __restrict__ eb3,
    float* __restrict__ out_bonds, int n_bonds)
{
    extern __shared__ char smem[];
    const uint32_t sb = smem_u32(smem);
    const int tid  = threadIdx.x;
    const int wid  = tid >> 5;
    const int lane = tid & 31;
    const int g = lane >> 2, t = lane & 3;
    const int wm = wid >> 1, wn = wid & 1;   // 4 pairs x 2 n-warps
    const int base = blockIdx.x * TMROWS;

    float* Bs  = (float*)(smem + B_BIAS);
    int*   A1s = (int*)(smem + B_A1S);
    uint32_t* Xh = (uint32_t*)(smem + B_XB);
    uint32_t* Xl = (uint32_t*)(smem + B_XB + 17408);
    // pair-local H (inside own X range)
    uint32_t* Hh = Xh + wm * 1088;
    uint32_t* Hl = Xl + wm * 1088;
    float*    H3 = (float*)(smem + B_XB + 34816);

    // weights -> smem (cp.async)
    for (int i = tid; i < 31232 / 16; i += NT)
        cp16(sb + B_WB + i * 16, (const char*)g_we + i * 16);
    CP_COMMIT();
    if (tid < 64) { Bs[tid] = eb1[tid]; Bs[64 + tid] = eb2[tid]; }
    else if (tid < 96) Bs[128 + tid - 64] = eb3[tid - 64];

    // ---- stage X: 64 rows x 4 quarters ----
    {
        const int m = tid >> 2, q = tid & 3;
        const int gid = base + m;
        const float* src;
        if (q == 0) {
            int a1 = ba1[gid];
            A1s[m] = a1;
            atomicAdd(&g_cnt[a1], 1.0f);
            src = atoms + (size_t)a1 * 32;
        } else if (q == 1) {
            src = atoms + (size_t)ba2[gid] * 32;
        } else if (q == 2) {
            src = bonds + (size_t)gid * 32;
        } else {
            src = state;
        }
        const int wbase = m * 68 + q * 16;
#pragma unroll
        for (int p = 0; p < 8; p++) {
            float4 v = *(const float4*)(src + 4 * p);
            uint32_t hw, lw;
            split_pair(v.x, v.y, hw, lw);
            Xh[wbase + 2 * p] = hw; Xl[wbase + 2 * p] = lw;
            split_pair(v.z, v.w, hw, lw);
            Xh[wbase + 2 * p + 1] = hw; Xl[wbase + 2 * p + 1] = lw;
        }
    }
    CP_WAIT0();
    __syncthreads();

    // lane-resolved fragment offsets
    const uint32_t a_loc = (uint32_t)(lane & 15);          // local row in pair
    const uint32_t a_kb  = (uint32_t)((lane >> 4) << 4);
    const uint32_t b_row = (uint32_t)(((lane >> 4) << 3) + (lane & 7));
    const uint32_t b_kb  = (uint32_t)(((lane >> 3) & 1) << 4);
    const uint32_t hb_h  = sb + B_XB + (uint32_t)wm * 4352;          // pair H hi base
    const uint32_t hb_l  = sb + B_XB + 17408 + (uint32_t)wm * 4352;  // pair H lo base

    // ---- layer 1: K=128 (X stride 272B), W1 stride 272B ----
    {
        float acc[4][4];
        uint32_t ao = ((uint32_t)(wm * 16) + a_loc) * 272 + a_kb;
        uint32_t bo = (wn * 32 + b_row) * 272 + b_kb;
        mlp_layer<8, 4>(sb + B_XB + ao, sb + B_XB + 17408 + ao,
                        sb + B_WB + bo, 272, acc);
        PAIR_BAR(wm);  // pair done reading its X rows
        epi_to_h<4>(acc, Bs, Hh, Hl, wn, g, t);
    }
    PAIR_BAR(wm);

    // ---- layer 2: K=64 (H stride 144B), W2 stride 144B ----
    {
        float acc[4][4];
        uint32_t ao = a_loc * 144 + a_kb;
        uint32_t bo = (wn * 32 + b_row) * 144 + b_kb;
        mlp_layer<4, 4>(hb_h + ao, hb_l + ao,
                        sb + B_WB + 17408 + bo, 144, acc);
        PAIR_BAR(wm);  // pair done reading H1
        epi_to_h<4>(acc, Bs + 64, Hh, Hl, wn, g, t);
    }
    PAIR_BAR(wm);

    // ---- layer 3: K=64, N=32 -> H3 staging + register bsum partials ----
    {
        float acc[2][4];
        uint32_t ao = a_loc * 144 + a_kb;
        uint32_t bo = (wn * 16 + b_row) * 144 + b_kb;
        mlp_layer<4, 2>(hb_h + ao, hb_l + ao,
                        sb + B_WB + 26624 + bo, 144, acc);

        const int r0 = wm * 16 + g;
        float bp[4];
#pragma unroll
        for (int j = 0; j < 2; j++) {
            int col = wn * 16 + j * 8 + 2 * t;
            float b0 = Bs[128 + col], b1 = Bs[128 + col + 1];
            float v0 = selu_f(acc[j][0] + b0);
            float v1 = selu_f(acc[j][1] + b1);
            float v2 = selu_f(acc[j][2] + b0);
            float v3 = selu_f(acc[j][3] + b1);
            float2 s;
            s.x = v0; s.y = v1;
            *(float2*)&H3[r0 * 36 + col] = s;
            s.x = v2; s.y = v3;
            *(float2*)&H3[(r0 + 8) * 36 + col] = s;
            bp[2 * j]     = v0 + v2;
            bp[2 * j + 1] = v1 + v3;
        }
        // shuffle-reduce partials over g (8 lanes), then RED (replaces serial loop)
#pragma unroll
        for (int mask = 4; mask <= 16; mask <<= 1)
#pragma unroll
            for (int q = 0; q < 4; q++)
                bp[q] += __shfl_xor_sync(0xffffffffu, bp[q], mask);
        if (g == 0) {
            int c0 = wn * 16 + 2 * t;
            atomicAdd(&g_bsum[c0],     bp[0]);
            atomicAdd(&g_bsum[c0 + 1], bp[1]);
            atomicAdd(&g_bsum[c0 + 8], bp[2]);
            atomicAdd(&g_bsum[c0 + 9], bp[3]);
        }
    }
    __syncthreads();

    // ---- outputs (coalesced via H3) ----
    for (int idx = tid; idx < TMROWS * 8; idx += NT) {
        int r = idx >> 3, f4 = idx & 7;
        float4 v = *(float4*)&H3[r * 36 + (f4 << 2)];
        *(float4*)&out_bonds[(size_t)(base + r) * 32 + (f4 << 2)] = v;
    }
    for (int r = wid; r < TMROWS; r += 8)
        atomicAdd(&g_b2a[(size_t)A1s[r] * 32 + lane], H3[r * 36 + lane]);
}

// ================= phi_v over atoms =================
__global__ void __launch_bounds__(NT, 3) atom_kernel(
    const float* __restrict__ atoms, const float* __restrict__ state,
    const float* __restrict__ vb1, const float* __restrict__ vb2,
    const float* __restrict__ vb3,
    float* __restrict__ out_atoms, int n_atoms)
{
    extern __shared__ char smem[];
    const uint32_t sb = smem_u32(smem);
    const int tid  = threadIdx.x;
    const int wid  = tid >> 5;
    const int lane = tid & 31;
    const int g = lane >> 2, t = lane & 3;
    const int wm = wid >> 1, wn = wid & 1;
    const int base = blockIdx.x * TMROWS;

    float* Bs = (float*)(smem + A_BIAS);
    uint32_t* Xh = (uint32_t*)(smem + A_XB);
    uint32_t* Xl = (uint32_t*)(smem + A_XB + 13312);
    uint32_t* Hh = Xh + wm * 832;   // pair X range = 16*52 = 832 words
    uint32_t* Hl = Xl + wm * 832;
    float*    H3 = (float*)(smem + A_XB + 26624);

    for (int i = tid; i < 27136 / 16; i += NT)
        cp16(sb + A_WB + i * 16, (const char*)g_wv + i * 16);
    CP_COMMIT();
    if (tid < 64) { Bs[tid] = vb1[tid]; Bs[64 + tid] = vb2[tid]; }
    else if (tid < 96) Bs[128 + tid - 64] = vb3[tid - 64];

    // ---- stage X: 64 rows x 3 thirds (quarter 3 idle) ----
    {
        const int m = tid >> 2, q = tid & 3;
        if (q < 3) {
            const int gm = base + m;
            const int id = gm < n_atoms ? gm : n_atoms - 1;
            const int wbase = m * 52 + q * 16;
            if (q == 0) {
                float inv = 1.0f / g_cnt[id];
#pragma unroll
                for (int p = 0; p < 8; p++) {
                    float4 v = *(const float4*)&g_b2a[(size_t)id * 32 + 4 * p];
                    uint32_t hw, lw;
                    split_pair(v.x * inv, v.y * inv, hw, lw);
                    Xh[wbase + 2 * p] = hw; Xl[wbase + 2 * p] = lw;
                    split_pair(v.z * inv, v.w * inv, hw, lw);
                    Xh[wbase + 2 * p + 1] = hw; Xl[wbase + 2 * p + 1] = lw;
                }
            } else {
                const float* src = (q == 1) ? atoms + (size_t)id * 32 : state;
#pragma unroll
                for (int p = 0; p < 8; p++) {
                    float4 v = *(const float4*)(src + 4 * p);
                    uint32_t hw, lw;
                    split_pair(v.x, v.y, hw, lw);
                    Xh[wbase + 2 * p] = hw; Xl[wbase + 2 * p] = lw;
                    split_pair(v.z, v.w, hw, lw);
                    Xh[wbase + 2 * p + 1] = hw; Xl[wbase + 2 * p + 1] = lw;
                }
            }
        }
    }
    CP_WAIT0();
    __syncthreads();

    const uint32_t a_loc = (uint32_t)(lane & 15);
    const uint32_t a_kb  = (uint32_t)((lane >> 4) << 4);
    const uint32_t b_row = (uint32_t)(((lane >> 4) << 3) + (lane & 7));
    const uint32_t b_kb  = (uint32_t)(((lane >> 3) & 1) << 4);
    const uint32_t hb_h  = sb + A_XB + (uint32_t)wm * 3328;
    const uint32_t hb_l  = sb + A_XB + 13312 + (uint32_t)wm * 3328;

    // ---- layer 1: K=96 (X stride 208B) ----
    {
        float acc[4][4];
        uint32_t ao = ((uint32_t)(wm * 16) + a_loc) * 208 + a_kb;
        uint32_t bo = (wn * 32 + b_row) * 208 + b_kb;
        mlp_layer<6, 4>(sb + A_XB + ao, sb + A_XB + 13312 + ao,
                        sb + A_WB + bo, 208, acc);
        PAIR_BAR(wm);
        epi_to_h<4>(acc, Bs, Hh, Hl, wn, g, t);
    }
    PAIR_BAR(wm);

    // ---- layer 2 ----
    {
        float acc[4][4];
        uint32_t ao = a_loc * 144 + a_kb;
        uint32_t bo = (wn * 32 + b_row) * 144 + b_kb;
        mlp_layer<4, 4>(hb_h + ao, hb_l + ao,
                        sb + A_WB + 13312 + bo, 144, acc);
        PAIR_BAR(wm);
        epi_to_h<4>(acc, Bs + 64, Hh, Hl, wn, g, t);
    }
    PAIR_BAR(wm);

    // ---- layer 3 -> H3 staging + register asum partials ----
    {
        float acc[2][4];
        uint32_t ao = a_loc * 144 + a_kb;
        uint32_t bo = (wn * 16 + b_row) * 144 + b_kb;
        mlp_layer<4, 2>(hb_h + ao, hb_l + ao,
                        sb + A_WB + 22528 + bo, 144, acc);

        const int r0 = wm * 16 + g;
        const bool v0ok = (base + r0) < n_atoms;
        const bool v1ok = (base + r0 + 8) < n_atoms;
        float ap[4];
#pragma unroll
        for (int j = 0; j < 2; j++) {
            int col = wn * 16 + j * 8 + 2 * t;
            float b0 = Bs[128 + col], b1 = Bs[128 + col + 1];
            float v0 = selu_f(acc[j][0] + b0);
            float v1 = selu_f(acc[j][1] + b1);
            float v2 = selu_f(acc[j][2] + b0);
            float v3 = selu_f(acc[j][3] + b1);
            float2 s;
            s.x = v0; s.y = v1;
            *(float2*)&H3[r0 * 36 + col] = s;
            s.x = v2; s.y = v3;
            *(float2*)&H3[(r0 + 8) * 36 + col] = s;
            ap[2 * j]     = (v0ok ? v0 : 0.f) + (v1ok ? v2 : 0.f);
            ap[2 * j + 1] = (v0ok ? v1 : 0.f) + (v1ok ? v3 : 0.f);
        }
#pragma unroll
        for (int mask = 4; mask <= 16; mask <<= 1)
#pragma unroll
            for (int q = 0; q < 4; q++)
                ap[q] += __shfl_xor_sync(0xffffffffu, ap[q], mask);
        if (g == 0) {
            int c0 = wn * 16 + 2 * t;
            atomicAdd(&g_asum[c0],     ap[0]);
            atomicAdd(&g_asum[c0 + 1], ap[1]);
            atomicAdd(&g_asum[c0 + 8], ap[2]);
            atomicAdd(&g_asum[c0 + 9], ap[3]);
        }
    }
    __syncthreads();

    for (int idx = tid; idx < TMROWS * 8; idx += NT) {
        int r = idx >> 3, f4 = idx & 7;
        if (base + r < n_atoms) {
            float4 v = *(float4*)&H3[r * 36 + (f4 << 2)];
            *(float4*)&out_atoms[(size_t)(base + r) * 32 + (f4 << 2)] = v;
        }
    }
}

// ================= phi_u =================
__global__ void state_kernel(
    const float* __restrict__ state,
    const float* __restrict__ uw1, const float* __restrict__ ub1,
    const float* __restrict__ uw2, const float* __restrict__ ub2,
    const float* __restrict__ uw3, const float* __restrict__ ub3,
    float* __restrict__ out_state, int n_bonds, int n_atoms)
{
    __shared__ float x[96], h1[64], h2[64];
    int tid = threadIdx.x;  // 64 threads
    if (tid < 32) {
        x[tid]      = g_bsum[tid] / (float)n_bonds;
        x[32 + tid] = g_asum[tid] / (float)n_atoms;
        x[64 + tid] = state[tid];
    }
    __syncthreads();
    {
        float a = ub1[tid];
        for (int k = 0; k < 96; k++) a = fmaf(x[k], uw1[k * 64 + tid], a);
        h1[tid] = selu_f(a);
    }
    __syncthreads();
    {
        float a = ub2[tid];
        for (int k = 0; k < 64; k++) a = fmaf(h1[k], uw2[k * 64 + tid], a);
        h2[tid] = selu_f(a);
    }
    __syncthreads();
    if (tid < 32) {
        float a = ub3[tid];
        for (int k = 0; k < 64; k++) a = fmaf(h2[k], uw3[k * 32 + tid], a);
        out_state[tid] = selu_f(a);
    }
}

// ================= launch =================
extern "C" void kernel_launch(void* const* d_in, const int* in_sizes, int n_in,
                              void* d_out, int out_size)
{
    const float* bonds = (const float*)d_in[0];
    const int*   ba1   = (const int*)d_in[1];
    const int*   ba2   = (const int*)d_in[2];
    const float* atoms = (const float*)d_in[3];
    const float* state = (const float*)d_in[4];
    const float* ew1 = (const float*)d_in[5];
    const float* eb1 = (const float*)d_in[6];
    const float* ew2 = (const float*)d_in[7];
    const float* eb2 = (const float*)d_in[8];
    const float* ew3 = (const float*)d_in[9];
    const float* eb3 = (const float*)d_in[10];
    const float* vw1 = (const float*)d_in[11];
    const float* vb1 = (const float*)d_in[12];
    const float* vw2 = (const float*)d_in[13];
    const float* vb2 = (const float*)d_in[14];
    const float* vw3 = (const float*)d_in[15];
    const float* vb3 = (const float*)d_in[16];
    const float* uw1 = (const float*)d_in[17];
    const float* ub1 = (const float*)d_in[18];
    const float* uw2 = (const float*)d_in[19];
    const float* ub2 = (const float*)d_in[20];
    const float* uw3 = (const float*)d_in[21];
    const float* ub3 = (const float*)d_in[22];

    const int n_bonds = in_sizes[1];
    const int n_atoms = in_sizes[3] / 32;

    float* out       = (float*)d_out;
    float* out_bonds = out;
    float* out_atoms = out + (size_t)n_bonds * 32;
    float* out_state = out_atoms + (size_t)n_atoms * 32;

    cudaFuncSetAttribute(bond_kernel, cudaFuncAttributeMaxDynamicSharedMemorySize, B_SMEM);
    cudaFuncSetAttribute(atom_kernel, cudaFuncAttributeMaxDynamicSharedMemorySize, A_SMEM);

    zero_kernel<<<256, 256>>>(n_atoms);
    prep_kernel<<<(29184 + 255) / 256, 256>>>(ew1, ew2, ew3, vw1, vw2, vw3);

    int bond_blocks = n_bonds / TMROWS;
    bond_kernel<<<bond_blocks, NT, B_SMEM>>>(
        bonds, ba1, ba2, atoms, state, eb1, eb2, eb3, out_bonds, n_bonds);

    int atom_blocks = (n_atoms + TMROWS - 1) / TMROWS;
    atom_kernel<<<atom_blocks, NT, A_SMEM>>>(
        atoms, state, vb1, vb2, vb3, out_atoms, n_atoms);

    state_kernel<<<1, 64>>>(state, uw1, ub1, uw2, ub2, uw3, ub3,
                            out_state, n_bonds, n_atoms);
}

// round 13
// speedup vs baseline: 1.4435x; 1.2643x over previous
#include <cuda_runtime.h>
#include <cuda_fp16.h>
#include <math.h>
#include <stdint.h>

// ================= scratch (no allocations allowed) =================
#define MAX_ATOMS 100000
__device__ float g_b2a[MAX_ATOMS * 32];
__device__ float g_cnt[MAX_ATOMS];
__device__ float g_bsum[32];
__device__ float g_asum[32];

// pre-transposed fp16 weight images Wt[n][k], padded k-stride
__device__ __align__(16) __half g_we[15616];  // W1@0 W2@8704 W3@13312 (halves)
__device__ __align__(16) __half g_wv[13568];  // V1@0 V2@6656 V3@11264

__device__ __forceinline__ float selu_f(float x) {
    const float lam = 1.0507009873554805f;
    const float la  = 1.7580993408473766f;
    float e = __expf(x);
    return x > 0.f ? lam * x : fmaf(la, e, -la);
}

// fp32 pair -> fp16x2 hi word + fp16x2 residual word (packed cvt)
__device__ __forceinline__ void split_pair(float v0, float v1, uint32_t& hw, uint32_t& lw) {
    __half2 hp = __floats2half2_rn(v0, v1);
    float2 hf = __half22float2(hp);
    __half2 lp = __floats2half2_rn(v0 - hf.x, v1 - hf.y);
    hw = *(uint32_t*)&hp;
    lw = *(uint32_t*)&lp;
}

__device__ __forceinline__ uint32_t smem_u32(const void* p) {
    uint32_t a;
    asm("{ .reg .u64 t; cvta.to.shared.u64 t, %1; cvt.u32.u64 %0, t; }" : "=r"(a) : "l"(p));
    return a;
}

// ---- baseline-ISA ops (valid on plain sm_100) ----
__device__ __forceinline__ void ldmx4(uint32_t r[4], uint32_t addr) {
    asm volatile("ldmatrix.sync.aligned.m8n8.x4.shared.b16 {%0,%1,%2,%3}, [%4];"
        : "=r"(r[0]), "=r"(r[1]), "=r"(r[2]), "=r"(r[3]) : "r"(addr));
}
__device__ __forceinline__ void mma_f16(float c[4], const uint32_t a[4], uint32_t b0, uint32_t b1) {
    asm("mma.sync.aligned.m16n8k16.row.col.f32.f16.f16.f32 "
        "{%0,%1,%2,%3}, {%4,%5,%6,%7}, {%8,%9}, {%0,%1,%2,%3};"
        : "+f"(c[0]), "+f"(c[1]), "+f"(c[2]), "+f"(c[3])
        : "r"(a[0]), "r"(a[1]), "r"(a[2]), "r"(a[3]), "r"(b0), "r"(b1));
}
__device__ __forceinline__ void cp16(uint32_t dst, const void* src) {
    asm volatile("cp.async.ca.shared.global [%0], [%1], 16;" :: "r"(dst), "l"(src));
}
#define CP_COMMIT() asm volatile("cp.async.commit_group;" ::: "memory")
#define CP_WAIT0()  asm volatile("cp.async.wait_group 0;" ::: "memory")
// pair-scoped barrier: 2 warps (64 threads), ids 1..4
#define PAIR_BAR(wm) asm volatile("bar.sync %0, 64;" :: "r"((wm) + 1) : "memory")

// dense layer: acc[NTW][4] += A(16 rows x K) @ Wt^T  (fp16 2-pass)
template <int KS, int NTW>
__device__ __forceinline__ void mlp_layer(
    uint32_t xh_addr, uint32_t xl_addr,
    uint32_t b_addr, uint32_t sbwB,
    float acc[NTW][4])
{
#pragma unroll
    for (int j = 0; j < NTW; j++)
#pragma unroll
        for (int q = 0; q < 4; q++) acc[j][q] = 0.f;

#pragma unroll
    for (int k = 0; k < KS; k++) {
        uint32_t ah[4], al[4];
        ldmx4(ah, xh_addr);
        ldmx4(al, xl_addr);
        xh_addr += 32; xl_addr += 32;
#pragma unroll
        for (int p = 0; p < NTW / 2; p++) {
            uint32_t rw[4];
            ldmx4(rw, b_addr + p * 8 * sbwB * 2);
            mma_f16(acc[2 * p],     ah, rw[0], rw[1]);
            mma_f16(acc[2 * p + 1], ah, rw[2], rw[3]);
            mma_f16(acc[2 * p],     al, rw[0], rw[1]);
            mma_f16(acc[2 * p + 1], al, rw[2], rw[3]);
        }
        b_addr += 32;
    }
}

// epilogue: bias+selu -> split -> pair-LOCAL fp16 H images (rows 0..15, stride 36 words)
template <int NTW>
__device__ __forceinline__ void epi_to_h(
    float acc[NTW][4], const float* bias,
    uint32_t* Hh, uint32_t* Hl, int wn, int g, int t)
{
    const int r0 = g;  // local row within pair
#pragma unroll
    for (int j = 0; j < NTW; j++) {
        int col = wn * 32 + j * 8 + 2 * t;
        int cw  = wn * 16 + j * 4 + t;
        float b0 = bias[col], b1 = bias[col + 1];
        uint32_t hw, lw;
        split_pair(selu_f(acc[j][0] + b0), selu_f(acc[j][1] + b1), hw, lw);
        Hh[r0 * 36 + cw] = hw; Hl[r0 * 36 + cw] = lw;
        split_pair(selu_f(acc[j][2] + b0), selu_f(acc[j][3] + b1), hw, lw);
        Hh[(r0 + 8) * 36 + cw] = hw; Hl[(r0 + 8) * 36 + cw] = lw;
    }
}

// epilogue: bias+selu -> fp32 H3 [64][36] (global rows), N=32
__device__ __forceinline__ void epi_to_f32(
    float acc[2][4], const float* bias, float* H3, int wm, int wn, int g, int t)
{
    const int r0 = wm * 16 + g;
#pragma unroll
    for (int j = 0; j < 2; j++) {
        int col = wn * 16 + j * 8 + 2 * t;
        float b0 = bias[col], b1 = bias[col + 1];
        float2 v;
        v.x = selu_f(acc[j][0] + b0);
        v.y = selu_f(acc[j][1] + b1);
        *(float2*)&H3[r0 * 36 + col] = v;
        v.x = selu_f(acc[j][2] + b0);
        v.y = selu_f(acc[j][3] + b1);
        *(float2*)&H3[(r0 + 8) * 36 + col] = v;
    }
}

// ================= zero scratch =================
__global__ void zero_kernel(int n_atoms)
{
    int i = blockIdx.x * blockDim.x + threadIdx.x;
    int stride = gridDim.x * blockDim.x;
    int nb = n_atoms * 32;
    for (int idx = i; idx < nb; idx += stride) g_b2a[idx] = 0.f;
    for (int idx = i; idx < n_atoms; idx += stride) g_cnt[idx] = 0.f;
    if (i < 32) { g_bsum[i] = 0.f; g_asum[i] = 0.f; }
}

// ================= weight transpose prep =================
__global__ void prep_kernel(
    const float* __restrict__ ew1, const float* __restrict__ ew2, const float* __restrict__ ew3,
    const float* __restrict__ vw1, const float* __restrict__ vw2, const float* __restrict__ vw3)
{
    int i = blockIdx.x * blockDim.x + threadIdx.x;
    if (i >= 29184) return;
    const float* src; __half* img;
    int stride, N, Ksrc, local;
    if (i < 8704)        { local = i;         stride = 136; N = 64; Ksrc = 128; src = ew1; img = g_we; }
    else if (i < 13312)  { local = i - 8704;  stride = 72;  N = 64; Ksrc = 64;  src = ew2; img = g_we + 8704; }
    else if (i < 15616)  { local = i - 13312; stride = 72;  N = 32; Ksrc = 64;  src = ew3; img = g_we + 13312; }
    else if (i < 22272)  { local = i - 15616; stride = 104; N = 64; Ksrc = 96;  src = vw1; img = g_wv; }
    else if (i < 26880)  { local = i - 22272; stride = 72;  N = 64; Ksrc = 64;  src = vw2; img = g_wv + 6656; }
    else                 { local = i - 26880; stride = 72;  N = 32; Ksrc = 64;  src = vw3; img = g_wv + 11264; }
    int n = local / stride, k = local % stride;
    float w = (k < Ksrc) ? src[k * N + n] : 0.f;
    img[local] = __float2half(w);
}

// ================= smem maps (bytes) =================
// bond: Xh 17408 + Xl 17408 (pair's H overlays its own 4352B X range)
// H3 @ B_XB+34816 (9216); weights @ B_XB+44032 (31232)
#define B_BIAS   0
#define B_A1S    640
#define B_XB     1024
#define B_WB     45056
#define B_SMEM   76288
// atom: Xh 13312 + Xl 13312; H3 @ A_XB+26624; weights @ 36608
#define A_BIAS   0
#define A_XB     768
#define A_WB     36608
#define A_SMEM   63744

#define NT 256
#define TMROWS 64

// ================= phi_e over bonds =================
__global__ void __launch_bounds__(NT, 3) bond_kernel(
    const float* __restrict__ bonds, const int* __restrict__ ba1,
    const int* __restrict__ ba2, const float* __restrict__ atoms,
    const float* __restrict__ state,
    const float* __restrict__ eb1, const float* __restrict__ eb2,
    const float* __restrict__ eb3,
    float* __restrict__ out_bonds, int n_bonds)
{
    extern __shared__ char smem[];
    const uint32_t sb = smem_u32(smem);
    const int tid  = threadIdx.x;
    const int wid  = tid >> 5;
    const int lane = tid & 31;
    const int g = lane >> 2, t = lane & 3;
    const int wm = wid >> 1, wn = wid & 1;   // 4 pairs x 2 n-warps
    const int base = blockIdx.x * TMROWS;

    float* Bs  = (float*)(smem + B_BIAS);
    int*   A1s = (int*)(smem + B_A1S);
    uint32_t* Xh = (uint32_t*)(smem + B_XB);
    uint32_t* Xl = (uint32_t*)(smem + B_XB + 17408);
    // pair-local H (inside own X range)
    uint32_t* Hh = Xh + wm * 1088;
    uint32_t* Hl = Xl + wm * 1088;
    float*    H3 = (float*)(smem + B_XB + 34816);

    // weights -> smem (cp.async)
    for (int i = tid; i < 31232 / 16; i += NT)
        cp16(sb + B_WB + i * 16, (const char*)g_we + i * 16);
    CP_COMMIT();
    if (tid < 64) { Bs[tid] = eb1[tid]; Bs[64 + tid] = eb2[tid]; }
    else if (tid < 96) Bs[128 + tid - 64] = eb3[tid - 64];

    // ---- stage X: 64 rows x 4 quarters ----
    {
        const int m = tid >> 2, q = tid & 3;
        const int gid = base + m;
        const float* src;
        if (q == 0) {
            int a1 = ba1[gid];
            A1s[m] = a1;
            atomicAdd(&g_cnt[a1], 1.0f);
            src = atoms + (size_t)a1 * 32;
        } else if (q == 1) {
            src = atoms + (size_t)ba2[gid] * 32;
        } else if (q == 2) {
            src = bonds + (size_t)gid * 32;
        } else {
            src = state;
        }
        const int wbase = m * 68 + q * 16;
#pragma unroll
        for (int p = 0; p < 8; p++) {
            float4 v = *(const float4*)(src + 4 * p);
            uint32_t hw, lw;
            split_pair(v.x, v.y, hw, lw);
            Xh[wbase + 2 * p] = hw; Xl[wbase + 2 * p] = lw;
            split_pair(v.z, v.w, hw, lw);
            Xh[wbase + 2 * p + 1] = hw; Xl[wbase + 2 * p + 1] = lw;
        }
    }
    CP_WAIT0();
    __syncthreads();

    // lane-resolved fragment offsets
    const uint32_t a_loc = (uint32_t)(lane & 15);          // local row in pair
    const uint32_t a_kb  = (uint32_t)((lane >> 4) << 4);
    const uint32_t b_row = (uint32_t)(((lane >> 4) << 3) + (lane & 7));
    const uint32_t b_kb  = (uint32_t)(((lane >> 3) & 1) << 4);
    const uint32_t hb_h  = sb + B_XB + (uint32_t)wm * 4352;          // pair H hi base
    const uint32_t hb_l  = sb + B_XB + 17408 + (uint32_t)wm * 4352;  // pair H lo base

    // ---- layer 1: K=128 (X stride 272B), W1 stride 272B ----
    {
        float acc[4][4];
        uint32_t ao = ((uint32_t)(wm * 16) + a_loc) * 272 + a_kb;
        uint32_t bo = (wn * 32 + b_row) * 272 + b_kb;
        mlp_layer<8, 4>(sb + B_XB + ao, sb + B_XB + 17408 + ao,
                        sb + B_WB + bo, 272, acc);
        PAIR_BAR(wm);  // pair done reading its X rows
        epi_to_h<4>(acc, Bs, Hh, Hl, wn, g, t);
    }
    PAIR_BAR(wm);

    // ---- layer 2: K=64 (H stride 144B), W2 stride 144B ----
    {
        float acc[4][4];
        uint32_t ao = a_loc * 144 + a_kb;
        uint32_t bo = (wn * 32 + b_row) * 144 + b_kb;
        mlp_layer<4, 4>(hb_h + ao, hb_l + ao,
                        sb + B_WB + 17408 + bo, 144, acc);
        PAIR_BAR(wm);  // pair done reading H1
        epi_to_h<4>(acc, Bs + 64, Hh, Hl, wn, g, t);
    }
    PAIR_BAR(wm);

    // ---- layer 3: K=64, N=32 ----
    {
        float acc[2][4];
        uint32_t ao = a_loc * 144 + a_kb;
        uint32_t bo = (wn * 16 + b_row) * 144 + b_kb;
        mlp_layer<4, 2>(hb_h + ao, hb_l + ao,
                        sb + B_WB + 26624 + bo, 144, acc);
        epi_to_f32(acc, Bs + 128, H3, wm, wn, g, t);
    }
    __syncthreads();

    // ---- outputs ----
    for (int idx = tid; idx < TMROWS * 8; idx += NT) {
        int r = idx >> 3, f4 = idx & 7;
        float4 v = *(float4*)&H3[r * 36 + (f4 << 2)];
        *(float4*)&out_bonds[(size_t)(base + r) * 32 + (f4 << 2)] = v;
    }
    for (int r = wid; r < TMROWS; r += 8)
        atomicAdd(&g_b2a[(size_t)A1s[r] * 32 + lane], H3[r * 36 + lane]);
    if (tid < 32) {
        float ssum = 0.f;
        for (int r = 0; r < TMROWS; r++) ssum += H3[r * 36 + tid];
        atomicAdd(&g_bsum[tid], ssum);
    }
}

// ================= phi_v over atoms =================
__global__ void __launch_bounds__(NT, 3) atom_kernel(
    const float* __restrict__ atoms, const float* __restrict__ state,
    const float* __restrict__ vb1, const float* __restrict__ vb2,
    const float* __restrict__ vb3,
    float* __restrict__ out_atoms, int n_atoms)
{
    extern __shared__ char smem[];
    const uint32_t sb = smem_u32(smem);
    const int tid  = threadIdx.x;
    const int wid  = tid >> 5;
    const int lane = tid & 31;
    const int g = lane >> 2, t = lane & 3;
    const int wm = wid >> 1, wn = wid & 1;
    const int base = blockIdx.x * TMROWS;

    float* Bs = (float*)(smem + A_BIAS);
    uint32_t* Xh = (uint32_t*)(smem + A_XB);
    uint32_t* Xl = (uint32_t*)(smem + A_XB + 13312);
    uint32_t* Hh = Xh + wm * 832;   // pair X range = 16*52 = 832 words
    uint32_t* Hl = Xl + wm * 832;
    float*    H3 = (float*)(smem + A_XB + 26624);

    for (int i = tid; i < 27136 / 16; i += NT)
        cp16(sb + A_WB + i * 16, (const char*)g_wv + i * 16);
    CP_COMMIT();
    if (tid < 64) { Bs[tid] = vb1[tid]; Bs[64 + tid] = vb2[tid]; }
    else if (tid < 96) Bs[128 + tid - 64] = vb3[tid - 64];

    // ---- stage X: 64 rows x 3 thirds (quarter 3 idle) ----
    {
        const int m = tid >> 2, q = tid & 3;
        if (q < 3) {
            const int gm = base + m;
            const int id = gm < n_atoms ? gm : n_atoms - 1;
            const int wbase = m * 52 + q * 16;
            if (q == 0) {
                float inv = 1.0f / g_cnt[id];
#pragma unroll
                for (int p = 0; p < 8; p++) {
                    float4 v = *(const float4*)&g_b2a[(size_t)id * 32 + 4 * p];
                    uint32_t hw, lw;
                    split_pair(v.x * inv, v.y * inv, hw, lw);
                    Xh[wbase + 2 * p] = hw; Xl[wbase + 2 * p] = lw;
                    split_pair(v.z * inv, v.w * inv, hw, lw);
                    Xh[wbase + 2 * p + 1] = hw; Xl[wbase + 2 * p + 1] = lw;
                }
            } else {
                const float* src = (q == 1) ? atoms + (size_t)id * 32 : state;
#pragma unroll
                for (int p = 0; p < 8; p++) {
                    float4 v = *(const float4*)(src + 4 * p);
                    uint32_t hw, lw;
                    split_pair(v.x, v.y, hw, lw);
                    Xh[wbase + 2 * p] = hw; Xl[wbase + 2 * p] = lw;
                    split_pair(v.z, v.w, hw, lw);
                    Xh[wbase + 2 * p + 1] = hw; Xl[wbase + 2 * p + 1] = lw;
                }
            }
        }
    }
    CP_WAIT0();
    __syncthreads();

    const uint32_t a_loc = (uint32_t)(lane & 15);
    const uint32_t a_kb  = (uint32_t)((lane >> 4) << 4);
    const uint32_t b_row = (uint32_t)(((lane >> 4) << 3) + (lane & 7));
    const uint32_t b_kb  = (uint32_t)(((lane >> 3) & 1) << 4);
    const uint32_t hb_h  = sb + A_XB + (uint32_t)wm * 3328;
    const uint32_t hb_l  = sb + A_XB + 13312 + (uint32_t)wm * 3328;

    // ---- layer 1: K=96 (X stride 208B) ----
    {
        float acc[4][4];
        uint32_t ao = ((uint32_t)(wm * 16) + a_loc) * 208 + a_kb;
        uint32_t bo = (wn * 32 + b_row) * 208 + b_kb;
        mlp_layer<6, 4>(sb + A_XB + ao, sb + A_XB + 13312 + ao,
                        sb + A_WB + bo, 208, acc);
        PAIR_BAR(wm);
        epi_to_h<4>(acc, Bs, Hh, Hl, wn, g, t);
    }
    PAIR_BAR(wm);

    // ---- layer 2 ----
    {
        float acc[4][4];
        uint32_t ao = a_loc * 144 + a_kb;
        uint32_t bo = (wn * 32 + b_row) * 144 + b_kb;
        mlp_layer<4, 4>(hb_h + ao, hb_l + ao,
                        sb + A_WB + 13312 + bo, 144, acc);
        PAIR_BAR(wm);
        epi_to_h<4>(acc, Bs + 64, Hh, Hl, wn, g, t);
    }
    PAIR_BAR(wm);

    // ---- layer 3 ----
    {
        float acc[2][4];
        uint32_t ao = a_loc * 144 + a_kb;
        uint32_t bo = (wn * 16 + b_row) * 144 + b_kb;
        mlp_layer<4, 2>(hb_h + ao, hb_l + ao,
                        sb + A_WB + 22528 + bo, 144, acc);
        epi_to_f32(acc, Bs + 128, H3, wm, wn, g, t);
    }
    __syncthreads();

    for (int idx = tid; idx < TMROWS * 8; idx += NT) {
        int r = idx >> 3, f4 = idx & 7;
        if (base + r < n_atoms) {
            float4 v = *(float4*)&H3[r * 36 + (f4 << 2)];
            *(float4*)&out_atoms[(size_t)(base + r) * 32 + (f4 << 2)] = v;
        }
    }
    if (tid < 32) {
        float ssum = 0.f;
        for (int r = 0; r < TMROWS; r++)
            if (base + r < n_atoms) ssum += H3[r * 36 + tid];
        atomicAdd(&g_asum[tid], ssum);
    }
}

// ================= phi_u =================
__global__ void state_kernel(
    const float* __restrict__ state,
    const float* __restrict__ uw1, const float* __restrict__ ub1,
    const float* __restrict__ uw2, const float* __restrict__ ub2,
    const float* __restrict__ uw3, const float* __restrict__ ub3,
    float* __restrict__ out_state, int n_bonds, int n_atoms)
{
    __shared__ float x[96], h1[64], h2[64];
    int tid = threadIdx.x;  // 64 threads
    if (tid < 32) {
        x[tid]      = g_bsum[tid] / (float)n_bonds;
        x[32 + tid] = g_asum[tid] / (float)n_atoms;
        x[64 + tid] = state[tid];
    }
    __syncthreads();
    {
        float a = ub1[tid];
        for (int k = 0; k < 96; k++) a = fmaf(x[k], uw1[k * 64 + tid], a);
        h1[tid] = selu_f(a);
    }
    __syncthreads();
    {
        float a = ub2[tid];
        for (int k = 0; k < 64; k++) a = fmaf(h1[k], uw2[k * 64 + tid], a);
        h2[tid] = selu_f(a);
    }
    __syncthreads();
    if (tid < 32) {
        float a = ub3[tid];
        for (int k = 0; k < 64; k++) a = fmaf(h2[k], uw3[k * 32 + tid], a);
        out_state[tid] = selu_f(a);
    }
}

// ================= launch =================
extern "C" void kernel_launch(void* const* d_in, const int* in_sizes, int n_in,
                              void* d_out, int out_size)
{
    const float* bonds = (const float*)d_in[0];
    const int*   ba1   = (const int*)d_in[1];
    const int*   ba2   = (const int*)d_in[2];
    const float* atoms = (const float*)d_in[3];
    const float* state = (const float*)d_in[4];
    const float* ew1 = (const float*)d_in[5];
    const float* eb1 = (const float*)d_in[6];
    const float* ew2 = (const float*)d_in[7];
    const float* eb2 = (const float*)d_in[8];
    const float* ew3 = (const float*)d_in[9];
    const float* eb3 = (const float*)d_in[10];
    const float* vw1 = (const float*)d_in[11];
    const float* vb1 = (const float*)d_in[12];
    const float* vw2 = (const float*)d_in[13];
    const float* vb2 = (const float*)d_in[14];
    const float* vw3 = (const float*)d_in[15];
    const float* vb3 = (const float*)d_in[16];
    const float* uw1 = (const float*)d_in[17];
    const float* ub1 = (const float*)d_in[18];
    const float* uw2 = (const float*)d_in[19];
    const float* ub2 = (const float*)d_in[20];
    const float* uw3 = (const float*)d_in[21];
    const float* ub3 = (const float*)d_in[22];

    const int n_bonds = in_sizes[1];
    const int n_atoms = in_sizes[3] / 32;

    float* out       = (float*)d_out;
    float* out_bonds = out;
    float* out_atoms = out + (size_t)n_bonds * 32;
    float* out_state = out_atoms + (size_t)n_atoms * 32;

    cudaFuncSetAttribute(bond_kernel, cudaFuncAttributeMaxDynamicSharedMemorySize, B_SMEM);
    cudaFuncSetAttribute(atom_kernel, cudaFuncAttributeMaxDynamicSharedMemorySize, A_SMEM);

    zero_kernel<<<256, 256>>>(n_atoms);
    prep_kernel<<<(29184 + 255) / 256, 256>>>(ew1, ew2, ew3, vw1, vw2, vw3);

    int bond_blocks = n_bonds / TMROWS;
    bond_kernel<<<bond_blocks, NT, B_SMEM>>>(
        bonds, ba1, ba2, atoms, state, eb1, eb2, eb3, out_bonds, n_bonds);

    int atom_blocks = (n_atoms + TMROWS - 1) / TMROWS;
    atom_kernel<<<atom_blocks, NT, A_SMEM>>>(
        atoms, state, vb1, vb2, vb3, out_atoms, n_atoms);

    state_kernel<<<1, 64>>>(state, uw1, ub1, uw2, ub2, uw3, ub3,
                            out_state, n_bonds, n_atoms);
}

// round 14
// speedup vs baseline: 1.5760x; 1.0917x over previous
#include <cuda_runtime.h>
#include <cuda_fp16.h>
#include <math.h>
#include <stdint.h>

// ================= scratch (no allocations allowed) =================
#define MAX_ATOMS 100000
__device__ float g_b2a[MAX_ATOMS * 32];
__device__ float g_cnt[MAX_ATOMS];
__device__ float g_bsum[32];
__device__ float g_asum[32];
__device__ float g_eb1f[64];   // fused bias: eb1 + state @ ew1[96:128]
__device__ float g_vb1f[64];   // fused bias: vb1 + state @ vw1[64:96]

// pre-transposed fp16 weight images Wt[n][k], padded k-stride
__device__ __align__(16) __half g_we[13568];  // W1(64x104)@0 W2(64x72)@6656 W3(32x72)@11264
__device__ __align__(16) __half g_wv[11520];  // V1(64x72)@0  V2(64x72)@4608 V3(32x72)@9216

__device__ __forceinline__ float selu_f(float x) {
    const float lam = 1.0507009873554805f;
    const float la  = 1.7580993408473766f;
    float e = __expf(x);
    return x > 0.f ? lam * x : fmaf(la, e, -la);
}

// fp32 pair -> fp16x2 hi word + fp16x2 residual word (packed cvt)
__device__ __forceinline__ void split_pair(float v0, float v1, uint32_t& hw, uint32_t& lw) {
    __half2 hp = __floats2half2_rn(v0, v1);
    float2 hf = __half22float2(hp);
    __half2 lp = __floats2half2_rn(v0 - hf.x, v1 - hf.y);
    hw = *(uint32_t*)&hp;
    lw = *(uint32_t*)&lp;
}

__device__ __forceinline__ uint32_t smem_u32(const void* p) {
    uint32_t a;
    asm("{ .reg .u64 t; cvta.to.shared.u64 t, %1; cvt.u32.u64 %0, t; }" : "=r"(a) : "l"(p));
    return a;
}

// ---- baseline-ISA ops (valid on plain sm_100) ----
__device__ __forceinline__ void ldmx4(uint32_t r[4], uint32_t addr) {
    asm volatile("ldmatrix.sync.aligned.m8n8.x4.shared.b16 {%0,%1,%2,%3}, [%4];"
        : "=r"(r[0]), "=r"(r[1]), "=r"(r[2]), "=r"(r[3]) : "r"(addr));
}
__device__ __forceinline__ void mma_f16(float c[4], const uint32_t a[4], uint32_t b0, uint32_t b1) {
    asm("mma.sync.aligned.m16n8k16.row.col.f32.f16.f16.f32 "
        "{%0,%1,%2,%3}, {%4,%5,%6,%7}, {%8,%9}, {%0,%1,%2,%3};"
        : "+f"(c[0]), "+f"(c[1]), "+f"(c[2]), "+f"(c[3])
        : "r"(a[0]), "r"(a[1]), "r"(a[2]), "r"(a[3]), "r"(b0), "r"(b1));
}
__device__ __forceinline__ void cp16(uint32_t dst, const void* src) {
    asm volatile("cp.async.ca.shared.global [%0], [%1], 16;" :: "r"(dst), "l"(src));
}
#define CP_COMMIT() asm volatile("cp.async.commit_group;" ::: "memory")
#define CP_WAIT0()  asm volatile("cp.async.wait_group 0;" ::: "memory")
// pair-scoped barrier: 2 warps (64 threads), ids 1..4
#define PAIR_BAR(wm) asm volatile("bar.sync %0, 64;" :: "r"((wm) + 1) : "memory")

// dense layer: acc[NTW][4] += A(16 rows x K) @ Wt^T  (fp16 2-pass)
template <int KS, int NTW>
__device__ __forceinline__ void mlp_layer(
    uint32_t xh_addr, uint32_t xl_addr,
    uint32_t b_addr, uint32_t sbwB,
    float acc[NTW][4])
{
#pragma unroll
    for (int j = 0; j < NTW; j++)
#pragma unroll
        for (int q = 0; q < 4; q++) acc[j][q] = 0.f;

#pragma unroll
    for (int k = 0; k < KS; k++) {
        uint32_t ah[4], al[4];
        ldmx4(ah, xh_addr);
        ldmx4(al, xl_addr);
        xh_addr += 32; xl_addr += 32;
#pragma unroll
        for (int p = 0; p < NTW / 2; p++) {
            uint32_t rw[4];
            ldmx4(rw, b_addr + p * 8 * sbwB * 2);
            mma_f16(acc[2 * p],     ah, rw[0], rw[1]);
            mma_f16(acc[2 * p + 1], ah, rw[2], rw[3]);
            mma_f16(acc[2 * p],     al, rw[0], rw[1]);
            mma_f16(acc[2 * p + 1], al, rw[2], rw[3]);
        }
        b_addr += 32;
    }
}

// epilogue: bias+selu -> split -> pair-LOCAL fp16 H images (rows 0..15, stride 36 words)
template <int NTW>
__device__ __forceinline__ void epi_to_h(
    float acc[NTW][4], const float* bias,
    uint32_t* Hh, uint32_t* Hl, int wn, int g, int t)
{
    const int r0 = g;  // local row within pair
#pragma unroll
    for (int j = 0; j < NTW; j++) {
        int col = wn * 32 + j * 8 + 2 * t;
        int cw  = wn * 16 + j * 4 + t;
        float b0 = bias[col], b1 = bias[col + 1];
        uint32_t hw, lw;
        split_pair(selu_f(acc[j][0] + b0), selu_f(acc[j][1] + b1), hw, lw);
        Hh[r0 * 36 + cw] = hw; Hl[r0 * 36 + cw] = lw;
        split_pair(selu_f(acc[j][2] + b0), selu_f(acc[j][3] + b1), hw, lw);
        Hh[(r0 + 8) * 36 + cw] = hw; Hl[(r0 + 8) * 36 + cw] = lw;
    }
}

// epilogue: bias+selu -> fp32 H3 [64][36] (global rows), N=32
__device__ __forceinline__ void epi_to_f32(
    float acc[2][4], const float* bias, float* H3, int wm, int wn, int g, int t)
{
    const int r0 = wm * 16 + g;
#pragma unroll
    for (int j = 0; j < 2; j++) {
        int col = wn * 16 + j * 8 + 2 * t;
        float b0 = bias[col], b1 = bias[col + 1];
        float2 v;
        v.x = selu_f(acc[j][0] + b0);
        v.y = selu_f(acc[j][1] + b1);
        *(float2*)&H3[r0 * 36 + col] = v;
        v.x = selu_f(acc[j][2] + b0);
        v.y = selu_f(acc[j][3] + b1);
        *(float2*)&H3[(r0 + 8) * 36 + col] = v;
    }
}

// ================= zero scratch =================
__global__ void zero_kernel(int n_atoms)
{
    int i = blockIdx.x * blockDim.x + threadIdx.x;
    int stride = gridDim.x * blockDim.x;
    int nb = n_atoms * 32;
    for (int idx = i; idx < nb; idx += stride) g_b2a[idx] = 0.f;
    for (int idx = i; idx < n_atoms; idx += stride) g_cnt[idx] = 0.f;
    if (i < 32) { g_bsum[i] = 0.f; g_asum[i] = 0.f; }
}

// ================= weight transpose prep + state-bias fold =================
__global__ void prep_kernel(
    const float* __restrict__ ew1, const float* __restrict__ ew2, const float* __restrict__ ew3,
    const float* __restrict__ vw1, const float* __restrict__ vw2, const float* __restrict__ vw3,
    const float* __restrict__ eb1, const float* __restrict__ vb1,
    const float* __restrict__ state)
{
    int i = blockIdx.x * blockDim.x + threadIdx.x;
    if (i < 25088) {
        const float* src; __half* img;
        int stride, N, Ksrc, local;
        if (i < 6656)        { local = i;         stride = 104; N = 64; Ksrc = 96; src = ew1; img = g_we; }
        else if (i < 11264)  { local = i - 6656;  stride = 72;  N = 64; Ksrc = 64; src = ew2; img = g_we + 6656; }
        else if (i < 13568)  { local = i - 11264; stride = 72;  N = 32; Ksrc = 64; src = ew3; img = g_we + 11264; }
        else if (i < 18176)  { local = i - 13568; stride = 72;  N = 64; Ksrc = 64; src = vw1; img = g_wv; }
        else if (i < 22784)  { local = i - 18176; stride = 72;  N = 64; Ksrc = 64; src = vw2; img = g_wv + 4608; }
        else                 { local = i - 22784; stride = 72;  N = 32; Ksrc = 64; src = vw3; img = g_wv + 9216; }
        int n = local / stride, k = local % stride;
        float w = (k < Ksrc) ? src[k * N + n] : 0.f;
        img[local] = __float2half(w);
    } else if (i < 25216) {
        // fused layer-1 biases (fp32 exact state contribution)
        int n = i - 25088;
        if (n < 64) {
            float a = eb1[n];
            for (int j = 0; j < 32; j++) a = fmaf(state[j], ew1[(96 + j) * 64 + n], a);
            g_eb1f[n] = a;
        } else {
            n -= 64;
            float a = vb1[n];
            for (int j = 0; j < 32; j++) a = fmaf(state[j], vw1[(64 + j) * 64 + n], a);
            g_vb1f[n] = a;
        }
    }
}

// ================= smem maps (bytes) =================
// bond: Xh 13312 + Xl 13312 (K=96, stride 208B); pair H overlays own X (832w >= 576w)
// H3 @ B_XB+26624 (9216); weights @ B_XB+35840: W1 13312, W2 @+13312, W3 @+22528
#define B_BIAS   0
#define B_A1S    640
#define B_XB     1024
#define B_WB     36864
#define B_SMEM   64000
// atom: Xh 9216 + Xl 9216 (K=64, stride 144B); pair H = pair X exactly (576w)
// H3 @ A_XB+18432 (9216); weights @ A_XB+27648: V1 9216, V2 @+9216, V3 @+18432
#define A_BIAS   0
#define A_XB     768
#define A_WB     28416
#define A_SMEM   51456

#define NT 256
#define TMROWS 64

// ================= phi_e over bonds =================
__global__ void __launch_bounds__(NT, 3) bond_kernel(
    const float* __restrict__ bonds, const int* __restrict__ ba1,
    const int* __restrict__ ba2, const float* __restrict__ atoms,
    const float* __restrict__ eb2, const float* __restrict__ eb3,
    float* __restrict__ out_bonds, int n_bonds)
{
    extern __shared__ char smem[];
    const uint32_t sb = smem_u32(smem);
    const int tid  = threadIdx.x;
    const int wid  = tid >> 5;
    const int lane = tid & 31;
    const int g = lane >> 2, t = lane & 3;
    const int wm = wid >> 1, wn = wid & 1;   // 4 pairs x 2 n-warps
    const int base = blockIdx.x * TMROWS;

    float* Bs  = (float*)(smem + B_BIAS);
    int*   A1s = (int*)(smem + B_A1S);
    uint32_t* Xh = (uint32_t*)(smem + B_XB);
    uint32_t* Xl = (uint32_t*)(smem + B_XB + 13312);
    // pair-local H (inside own X range: 16 rows x 52 words = 832 words/pair)
    uint32_t* Hh = Xh + wm * 832;
    uint32_t* Hl = Xl + wm * 832;
    float*    H3 = (float*)(smem + B_XB + 26624);

    // weights -> smem (cp.async), 27136 B
    for (int i = tid; i < 27136 / 16; i += NT)
        cp16(sb + B_WB + i * 16, (const char*)g_we + i * 16);
    CP_COMMIT();
    if (tid < 64) { Bs[tid] = g_eb1f[tid]; Bs[64 + tid] = eb2[tid]; }
    else if (tid < 96) Bs[128 + tid - 64] = eb3[tid - 64];

    // ---- stage X: 64 rows x 3 segments (a1 | a2 | bond), quarter 3 idle ----
    {
        const int m = tid >> 2, q = tid & 3;
        if (q < 3) {
            const int gid = base + m;
            const float* src;
            if (q == 0) {
                int a1 = ba1[gid];
                A1s[m] = a1;
                atomicAdd(&g_cnt[a1], 1.0f);
                src = atoms + (size_t)a1 * 32;
            } else if (q == 1) {
                src = atoms + (size_t)ba2[gid] * 32;
            } else {
                src = bonds + (size_t)gid * 32;
            }
            const int wbase = m * 52 + q * 16;
#pragma unroll
            for (int p = 0; p < 8; p++) {
                float4 v = *(const float4*)(src + 4 * p);
                uint32_t hw, lw;
                split_pair(v.x, v.y, hw, lw);
                Xh[wbase + 2 * p] = hw; Xl[wbase + 2 * p] = lw;
                split_pair(v.z, v.w, hw, lw);
                Xh[wbase + 2 * p + 1] = hw; Xl[wbase + 2 * p + 1] = lw;
            }
        }
    }
    CP_WAIT0();
    __syncthreads();

    // lane-resolved fragment offsets
    const uint32_t a_loc = (uint32_t)(lane & 15);          // local row in pair
    const uint32_t a_kb  = (uint32_t)((lane >> 4) << 4);
    const uint32_t b_row = (uint32_t)(((lane >> 4) << 3) + (lane & 7));
    const uint32_t b_kb  = (uint32_t)(((lane >> 3) & 1) << 4);
    const uint32_t hb_h  = sb + B_XB + (uint32_t)wm * 3328;          // pair H hi base
    const uint32_t hb_l  = sb + B_XB + 13312 + (uint32_t)wm * 3328;  // pair H lo base

    // ---- layer 1: K=96 (X stride 208B), W1 stride 208B ----
    {
        float acc[4][4];
        uint32_t ao = ((uint32_t)(wm * 16) + a_loc) * 208 + a_kb;
        uint32_t bo = (wn * 32 + b_row) * 208 + b_kb;
        mlp_layer<6, 4>(sb + B_XB + ao, sb + B_XB + 13312 + ao,
                        sb + B_WB + bo, 208, acc);
        PAIR_BAR(wm);  // pair done reading its X rows
        epi_to_h<4>(acc, Bs, Hh, Hl, wn, g, t);
    }
    PAIR_BAR(wm);

    // ---- layer 2: K=64 (H stride 144B), W2 stride 144B ----
    {
        float acc[4][4];
        uint32_t ao = a_loc * 144 + a_kb;
        uint32_t bo = (wn * 32 + b_row) * 144 + b_kb;
        mlp_layer<4, 4>(hb_h + ao, hb_l + ao,
                        sb + B_WB + 13312 + bo, 144, acc);
        PAIR_BAR(wm);  // pair done reading H1
        epi_to_h<4>(acc, Bs + 64, Hh, Hl, wn, g, t);
    }
    PAIR_BAR(wm);

    // ---- layer 3: K=64, N=32 ----
    {
        float acc[2][4];
        uint32_t ao = a_loc * 144 + a_kb;
        uint32_t bo = (wn * 16 + b_row) * 144 + b_kb;
        mlp_layer<4, 2>(hb_h + ao, hb_l + ao,
                        sb + B_WB + 22528 + bo, 144, acc);
        epi_to_f32(acc, Bs + 128, H3, wm, wn, g, t);
    }
    __syncthreads();

    // ---- outputs ----
    for (int idx = tid; idx < TMROWS * 8; idx += NT) {
        int r = idx >> 3, f4 = idx & 7;
        float4 v = *(float4*)&H3[r * 36 + (f4 << 2)];
        *(float4*)&out_bonds[(size_t)(base + r) * 32 + (f4 << 2)] = v;
    }
    for (int r = wid; r < TMROWS; r += 8)
        atomicAdd(&g_b2a[(size_t)A1s[r] * 32 + lane], H3[r * 36 + lane]);
    if (tid < 32) {
        float ssum = 0.f;
        for (int r = 0; r < TMROWS; r++) ssum += H3[r * 36 + tid];
        atomicAdd(&g_bsum[tid], ssum);
    }
}

// ================= phi_v over atoms =================
__global__ void __launch_bounds__(NT, 3) atom_kernel(
    const float* __restrict__ atoms,
    const float* __restrict__ vb2, const float* __restrict__ vb3,
    float* __restrict__ out_atoms, int n_atoms)
{
    extern __shared__ char smem[];
    const uint32_t sb = smem_u32(smem);
    const int tid  = threadIdx.x;
    const int wid  = tid >> 5;
    const int lane = tid & 31;
    const int g = lane >> 2, t = lane & 3;
    const int wm = wid >> 1, wn = wid & 1;
    const int base = blockIdx.x * TMROWS;

    float* Bs = (float*)(smem + A_BIAS);
    uint32_t* Xh = (uint32_t*)(smem + A_XB);
    uint32_t* Xl = (uint32_t*)(smem + A_XB + 9216);
    uint32_t* Hh = Xh + wm * 576;   // pair X range = 16*36 = 576 words (exact H fit)
    uint32_t* Hl = Xl + wm * 576;
    float*    H3 = (float*)(smem + A_XB + 18432);

    for (int i = tid; i < 23040 / 16; i += NT)
        cp16(sb + A_WB + i * 16, (const char*)g_wv + i * 16);
    CP_COMMIT();
    if (tid < 64) { Bs[tid] = g_vb1f[tid]; Bs[64 + tid] = vb2[tid]; }
    else if (tid < 96) Bs[128 + tid - 64] = vb3[tid - 64];

    // ---- stage X: 64 rows x 2 segments (b2a | atoms); tid<128 active ----
    if (tid < 128) {
        const int m = tid >> 1, q = tid & 1;
        const int gm = base + m;
        const int id = gm < n_atoms ? gm : n_atoms - 1;
        const int wbase = m * 36 + q * 16;
        if (q == 0) {
            float inv = 1.0f / g_cnt[id];
#pragma unroll
            for (int p = 0; p < 8; p++) {
                float4 v = *(const float4*)&g_b2a[(size_t)id * 32 + 4 * p];
                uint32_t hw, lw;
                split_pair(v.x * inv, v.y * inv, hw, lw);
                Xh[wbase + 2 * p] = hw; Xl[wbase + 2 * p] = lw;
                split_pair(v.z * inv, v.w * inv, hw, lw);
                Xh[wbase + 2 * p + 1] = hw; Xl[wbase + 2 * p + 1] = lw;
            }
        } else {
            const float* src = atoms + (size_t)id * 32;
#pragma unroll
            for (int p = 0; p < 8; p++) {
                float4 v = *(const float4*)(src + 4 * p);
                uint32_t hw, lw;
                split_pair(v.x, v.y, hw, lw);
                Xh[wbase + 2 * p] = hw; Xl[wbase + 2 * p] = lw;
                split_pair(v.z, v.w, hw, lw);
                Xh[wbase + 2 * p + 1] = hw; Xl[wbase + 2 * p + 1] = lw;
            }
        }
    }
    CP_WAIT0();
    __syncthreads();

    const uint32_t a_loc = (uint32_t)(lane & 15);
    const uint32_t a_kb  = (uint32_t)((lane >> 4) << 4);
    const uint32_t b_row = (uint32_t)(((lane >> 4) << 3) + (lane & 7));
    const uint32_t b_kb  = (uint32_t)(((lane >> 3) & 1) << 4);
    const uint32_t hb_h  = sb + A_XB + (uint32_t)wm * 2304;
    const uint32_t hb_l  = sb + A_XB + 9216 + (uint32_t)wm * 2304;

    // ---- layer 1: K=64 (X stride 144B), V1 stride 144B ----
    {
        float acc[4][4];
        uint32_t ao = ((uint32_t)(wm * 16) + a_loc) * 144 + a_kb;
        uint32_t bo = (wn * 32 + b_row) * 144 + b_kb;
        mlp_layer<4, 4>(sb + A_XB + ao, sb + A_XB + 9216 + ao,
                        sb + A_WB + bo, 144, acc);
        PAIR_BAR(wm);
        epi_to_h<4>(acc, Bs, Hh, Hl, wn, g, t);
    }
    PAIR_BAR(wm);

    // ---- layer 2 ----
    {
        float acc[4][4];
        uint32_t ao = a_loc * 144 + a_kb;
        uint32_t bo = (wn * 32 + b_row) * 144 + b_kb;
        mlp_layer<4, 4>(hb_h + ao, hb_l + ao,
                        sb + A_WB + 9216 + bo, 144, acc);
        PAIR_BAR(wm);
        epi_to_h<4>(acc, Bs + 64, Hh, Hl, wn, g, t);
    }
    PAIR_BAR(wm);

    // ---- layer 3 ----
    {
        float acc[2][4];
        uint32_t ao = a_loc * 144 + a_kb;
        uint32_t bo = (wn * 16 + b_row) * 144 + b_kb;
        mlp_layer<4, 2>(hb_h + ao, hb_l + ao,
                        sb + A_WB + 18432 + bo, 144, acc);
        epi_to_f32(acc, Bs + 128, H3, wm, wn, g, t);
    }
    __syncthreads();

    for (int idx = tid; idx < TMROWS * 8; idx += NT) {
        int r = idx >> 3, f4 = idx & 7;
        if (base + r < n_atoms) {
            float4 v = *(float4*)&H3[r * 36 + (f4 << 2)];
            *(float4*)&out_atoms[(size_t)(base + r) * 32 + (f4 << 2)] = v;
        }
    }
    if (tid < 32) {
        float ssum = 0.f;
        for (int r = 0; r < TMROWS; r++)
            if (base + r < n_atoms) ssum += H3[r * 36 + tid];
        atomicAdd(&g_asum[tid], ssum);
    }
}

// ================= phi_u =================
__global__ void state_kernel(
    const float* __restrict__ state,
    const float* __restrict__ uw1, const float* __restrict__ ub1,
    const float* __restrict__ uw2, const float* __restrict__ ub2,
    const float* __restrict__ uw3, const float* __restrict__ ub3,
    float* __restrict__ out_state, int n_bonds, int n_atoms)
{
    __shared__ float x[96], h1[64], h2[64];
    int tid = threadIdx.x;  // 64 threads
    if (tid < 32) {
        x[tid]      = g_bsum[tid] / (float)n_bonds;
        x[32 + tid] = g_asum[tid] / (float)n_atoms;
        x[64 + tid] = state[tid];
    }
    __syncthreads();
    {
        float a = ub1[tid];
        for (int k = 0; k < 96; k++) a = fmaf(x[k], uw1[k * 64 + tid], a);
        h1[tid] = selu_f(a);
    }
    __syncthreads();
    {
        float a = ub2[tid];
        for (int k = 0; k < 64; k++) a = fmaf(h1[k], uw2[k * 64 + tid], a);
        h2[tid] = selu_f(a);
    }
    __syncthreads();
    if (tid < 32) {
        float a = ub3[tid];
        for (int k = 0; k < 64; k++) a = fmaf(h2[k], uw3[k * 32 + tid], a);
        out_state[tid] = selu_f(a);
    }
}

// ================= launch =================
extern "C" void kernel_launch(void* const* d_in, const int* in_sizes, int n_in,
                              void* d_out, int out_size)
{
    const float* bonds = (const float*)d_in[0];
    const int*   ba1   = (const int*)d_in[1];
    const int*   ba2   = (const int*)d_in[2];
    const float* atoms = (const float*)d_in[3];
    const float* state = (const float*)d_in[4];
    const float* ew1 = (const float*)d_in[5];
    const float* eb1 = (const float*)d_in[6];
    const float* ew2 = (const float*)d_in[7];
    const float* eb2 = (const float*)d_in[8];
    const float* ew3 = (const float*)d_in[9];
    const float* eb3 = (const float*)d_in[10];
    const float* vw1 = (const float*)d_in[11];
    const float* vb1 = (const float*)d_in[12];
    const float* vw2 = (const float*)d_in[13];
    const float* vb2 = (const float*)d_in[14];
    const float* vw3 = (const float*)d_in[15];
    const float* vb3 = (const float*)d_in[16];
    const float* uw1 = (const float*)d_in[17];
    const float* ub1 = (const float*)d_in[18];
    const float* uw2 = (const float*)d_in[19];
    const float* ub2 = (const float*)d_in[20];
    const float* uw3 = (const float*)d_in[21];
    const float* ub3 = (const float*)d_in[22];

    const int n_bonds = in_sizes[1];
    const int n_atoms = in_sizes[3] / 32;

    float* out       = (float*)d_out;
    float* out_bonds = out;
    float* out_atoms = out + (size_t)n_bonds * 32;
    float* out_state = out_atoms + (size_t)n_atoms * 32;

    cudaFuncSetAttribute(bond_kernel, cudaFuncAttributeMaxDynamicSharedMemorySize, B_SMEM);
    cudaFuncSetAttribute(atom_kernel, cudaFuncAttributeMaxDynamicSharedMemorySize, A_SMEM);

    zero_kernel<<<256, 256>>>(n_atoms);
    prep_kernel<<<(25216 + 255) / 256, 256>>>(ew1, ew2, ew3, vw1, vw2, vw3,
                                              eb1, vb1, state);

    int bond_blocks = n_bonds / TMROWS;
    bond_kernel<<<bond_blocks, NT, B_SMEM>>>(
        bonds, ba1, ba2, atoms, eb2, eb3, out_bonds, n_bonds);

    int atom_blocks = (n_atoms + TMROWS - 1) / TMROWS;
    atom_kernel<<<atom_blocks, NT, A_SMEM>>>(
        atoms, vb2, vb3, out_atoms, n_atoms);

    state_kernel<<<1, 64>>>(state, uw1, ub1, uw2, ub2, uw3, ub3,
                            out_state, n_bonds, n_atoms);
}

// round 15
// speedup vs baseline: 1.6321x; 1.0357x over previous
#include <cuda_runtime.h>
#include <cuda_fp16.h>
#include <math.h>
#include <stdint.h>

// ================= scratch (no allocations allowed) =================
#define MAX_ATOMS 100000
__device__ float g_b2a[MAX_ATOMS * 32];
__device__ float g_cnt[MAX_ATOMS];
__device__ float g_bsum[32];
__device__ float g_asum[32];
__device__ float g_eb1f[64];   // fused bias: eb1 + state @ ew1[96:128]
__device__ float g_vb1f[64];   // fused bias: vb1 + state @ vw1[64:96]
// pre-split fp16 hi/lo images of the atoms table (L2-resident, built once)
__device__ __align__(16) __half g_ath[MAX_ATOMS * 32];
__device__ __align__(16) __half g_atl[MAX_ATOMS * 32];

// pre-transposed fp16 weight images Wt[n][k], padded k-stride
__device__ __align__(16) __half g_we[13568];  // W1(64x104)@0 W2(64x72)@6656 W3(32x72)@11264
__device__ __align__(16) __half g_wv[11520];  // V1(64x72)@0  V2(64x72)@4608 V3(32x72)@9216

__device__ __forceinline__ float selu_f(float x) {
    const float lam = 1.0507009873554805f;
    const float la  = 1.7580993408473766f;
    float e = __expf(x);
    return x > 0.f ? lam * x : fmaf(la, e, -la);
}

// fp32 pair -> fp16x2 hi word + fp16x2 residual word (packed cvt)
__device__ __forceinline__ void split_pair(float v0, float v1, uint32_t& hw, uint32_t& lw) {
    __half2 hp = __floats2half2_rn(v0, v1);
    float2 hf = __half22float2(hp);
    __half2 lp = __floats2half2_rn(v0 - hf.x, v1 - hf.y);
    hw = *(uint32_t*)&hp;
    lw = *(uint32_t*)&lp;
}

__device__ __forceinline__ uint32_t smem_u32(const void* p) {
    uint32_t a;
    asm("{ .reg .u64 t; cvta.to.shared.u64 t, %1; cvt.u32.u64 %0, t; }" : "=r"(a) : "l"(p));
    return a;
}

// ---- baseline-ISA ops (valid on plain sm_100) ----
__device__ __forceinline__ void ldmx4(uint32_t r[4], uint32_t addr) {
    asm volatile("ldmatrix.sync.aligned.m8n8.x4.shared.b16 {%0,%1,%2,%3}, [%4];"
        : "=r"(r[0]), "=r"(r[1]), "=r"(r[2]), "=r"(r[3]) : "r"(addr));
}
__device__ __forceinline__ void mma_f16(float c[4], const uint32_t a[4], uint32_t b0, uint32_t b1) {
    asm("mma.sync.aligned.m16n8k16.row.col.f32.f16.f16.f32 "
        "{%0,%1,%2,%3}, {%4,%5,%6,%7}, {%8,%9}, {%0,%1,%2,%3};"
        : "+f"(c[0]), "+f"(c[1]), "+f"(c[2]), "+f"(c[3])
        : "r"(a[0]), "r"(a[1]), "r"(a[2]), "r"(a[3]), "r"(b0), "r"(b1));
}
__device__ __forceinline__ void cp16(uint32_t dst, const void* src) {
    asm volatile("cp.async.ca.shared.global [%0], [%1], 16;" :: "r"(dst), "l"(src));
}
#define CP_COMMIT() asm volatile("cp.async.commit_group;" ::: "memory")
#define CP_WAIT0()  asm volatile("cp.async.wait_group 0;" ::: "memory")
// pair-scoped barrier: 2 warps (64 threads), ids 1..4
#define PAIR_BAR(wm) asm volatile("bar.sync %0, 64;" :: "r"((wm) + 1) : "memory")

// dense layer: acc[NTW][4] += A(16 rows x K) @ Wt^T  (fp16, TWO=2-pass hi+lo)
template <int KS, int NTW, bool TWO>
__device__ __forceinline__ void mlp_layer(
    uint32_t xh_addr, uint32_t xl_addr,
    uint32_t b_addr, uint32_t sbwB,
    float acc[NTW][4])
{
#pragma unroll
    for (int j = 0; j < NTW; j++)
#pragma unroll
        for (int q = 0; q < 4; q++) acc[j][q] = 0.f;

#pragma unroll
    for (int k = 0; k < KS; k++) {
        uint32_t ah[4], al[4];
        ldmx4(ah, xh_addr);
        if (TWO) ldmx4(al, xl_addr);
        xh_addr += 32; xl_addr += 32;
#pragma unroll
        for (int p = 0; p < NTW / 2; p++) {
            uint32_t rw[4];
            ldmx4(rw, b_addr + p * 8 * sbwB * 2);
            mma_f16(acc[2 * p],     ah, rw[0], rw[1]);
            mma_f16(acc[2 * p + 1], ah, rw[2], rw[3]);
            if (TWO) {
                mma_f16(acc[2 * p],     al, rw[0], rw[1]);
                mma_f16(acc[2 * p + 1], al, rw[2], rw[3]);
            }
        }
        b_addr += 32;
    }
}

// epilogue: bias+selu -> split -> pair-LOCAL fp16 H images (rows 0..15, stride 36 words)
template <int NTW>
__device__ __forceinline__ void epi_to_h(
    float acc[NTW][4], const float* bias,
    uint32_t* Hh, uint32_t* Hl, int wn, int g, int t)
{
    const int r0 = g;  // local row within pair
#pragma unroll
    for (int j = 0; j < NTW; j++) {
        int col = wn * 32 + j * 8 + 2 * t;
        int cw  = wn * 16 + j * 4 + t;
        float b0 = bias[col], b1 = bias[col + 1];
        uint32_t hw, lw;
        split_pair(selu_f(acc[j][0] + b0), selu_f(acc[j][1] + b1), hw, lw);
        Hh[r0 * 36 + cw] = hw; Hl[r0 * 36 + cw] = lw;
        split_pair(selu_f(acc[j][2] + b0), selu_f(acc[j][3] + b1), hw, lw);
        Hh[(r0 + 8) * 36 + cw] = hw; Hl[(r0 + 8) * 36 + cw] = lw;
    }
}

// epilogue: bias+selu -> fp32 H3 [64][36] (global rows), N=32
__device__ __forceinline__ void epi_to_f32(
    float acc[2][4], const float* bias, float* H3, int wm, int wn, int g, int t)
{
    const int r0 = wm * 16 + g;
#pragma unroll
    for (int j = 0; j < 2; j++) {
        int col = wn * 16 + j * 8 + 2 * t;
        float b0 = bias[col], b1 = bias[col + 1];
        float2 v;
        v.x = selu_f(acc[j][0] + b0);
        v.y = selu_f(acc[j][1] + b1);
        *(float2*)&H3[r0 * 36 + col] = v;
        v.x = selu_f(acc[j][2] + b0);
        v.y = selu_f(acc[j][3] + b1);
        *(float2*)&H3[(r0 + 8) * 36 + col] = v;
    }
}

// ================= zero scratch + atoms pre-split =================
__global__ void zero_kernel(const float* __restrict__ atoms, int n_atoms)
{
    int i = blockIdx.x * blockDim.x + threadIdx.x;
    int stride = gridDim.x * blockDim.x;
    int nb = n_atoms * 32;
    for (int idx = i; idx < nb; idx += stride) {
        g_b2a[idx] = 0.f;
        float v = atoms[idx];
        __half h = __float2half(v);
        g_ath[idx] = h;
        g_atl[idx] = __float2half(v - __half2float(h));
    }
    for (int idx = i; idx < n_atoms; idx += stride) g_cnt[idx] = 0.f;
    if (i < 32) { g_bsum[i] = 0.f; g_asum[i] = 0.f; }
}

// ================= weight transpose prep + state-bias fold =================
__global__ void prep_kernel(
    const float* __restrict__ ew1, const float* __restrict__ ew2, const float* __restrict__ ew3,
    const float* __restrict__ vw1, const float* __restrict__ vw2, const float* __restrict__ vw3,
    const float* __restrict__ eb1, const float* __restrict__ vb1,
    const float* __restrict__ state)
{
    int i = blockIdx.x * blockDim.x + threadIdx.x;
    if (i < 25088) {
        const float* src; __half* img;
        int stride, N, Ksrc, local;
        if (i < 6656)        { local = i;         stride = 104; N = 64; Ksrc = 96; src = ew1; img = g_we; }
        else if (i < 11264)  { local = i - 6656;  stride = 72;  N = 64; Ksrc = 64; src = ew2; img = g_we + 6656; }
        else if (i < 13568)  { local = i - 11264; stride = 72;  N = 32; Ksrc = 64; src = ew3; img = g_we + 11264; }
        else if (i < 18176)  { local = i - 13568; stride = 72;  N = 64; Ksrc = 64; src = vw1; img = g_wv; }
        else if (i < 22784)  { local = i - 18176; stride = 72;  N = 64; Ksrc = 64; src = vw2; img = g_wv + 4608; }
        else                 { local = i - 22784; stride = 72;  N = 32; Ksrc = 64; src = vw3; img = g_wv + 9216; }
        int n = local / stride, k = local % stride;
        float w = (k < Ksrc) ? src[k * N + n] : 0.f;
        img[local] = __float2half(w);
    } else if (i < 25216) {
        // fused layer-1 biases (fp32 exact state contribution)
        int n = i - 25088;
        if (n < 64) {
            float a = eb1[n];
            for (int j = 0; j < 32; j++) a = fmaf(state[j], ew1[(96 + j) * 64 + n], a);
            g_eb1f[n] = a;
        } else {
            n -= 64;
            float a = vb1[n];
            for (int j = 0; j < 32; j++) a = fmaf(state[j], vw1[(64 + j) * 64 + n], a);
            g_vb1f[n] = a;
        }
    }
}

// ================= smem maps (bytes) =================
// bond: Xh 13312 + Xl 13312 (K=96, stride 208B); pair H overlays own X (832w >= 576w)
// H3 @ B_XB+26624 (9216); weights @ B_XB+35840: W1 13312, W2 @+13312, W3 @+22528
#define B_BIAS   0
#define B_A1S    640
#define B_XB     1024
#define B_WB     36864
#define B_SMEM   64000
// atom: Xh 9216 + Xl 9216 (K=64, stride 144B); pair H = pair X exactly (576w)
// H3 @ A_XB+18432 (9216); weights @ A_XB+27648: V1 9216, V2 @+9216, V3 @+18432
#define A_BIAS   0
#define A_XB     768
#define A_WB     28416
#define A_SMEM   51456

#define NT 256
#define TMROWS 64

// ================= phi_e over bonds =================
__global__ void __launch_bounds__(NT, 3) bond_kernel(
    const float* __restrict__ bonds, const int* __restrict__ ba1,
    const int* __restrict__ ba2,
    const float* __restrict__ eb2, const float* __restrict__ eb3,
    float* __restrict__ out_bonds, int n_bonds)
{
    extern __shared__ char smem[];
    const uint32_t sb = smem_u32(smem);
    const int tid  = threadIdx.x;
    const int wid  = tid >> 5;
    const int lane = tid & 31;
    const int g = lane >> 2, t = lane & 3;
    const int wm = wid >> 1, wn = wid & 1;   // 4 pairs x 2 n-warps
    const int base = blockIdx.x * TMROWS;

    float* Bs  = (float*)(smem + B_BIAS);
    int*   A1s = (int*)(smem + B_A1S);
    uint32_t* Xh = (uint32_t*)(smem + B_XB);
    uint32_t* Xl = (uint32_t*)(smem + B_XB + 13312);
    // pair-local H (inside own X range: 16 rows x 52 words = 832 words/pair)
    uint32_t* Hh = Xh + wm * 832;
    uint32_t* Hl = Xl + wm * 832;
    float*    H3 = (float*)(smem + B_XB + 26624);

    // weights -> smem (cp.async), 27136 B
    for (int i = tid; i < 27136 / 16; i += NT)
        cp16(sb + B_WB + i * 16, (const char*)g_we + i * 16);
    CP_COMMIT();
    if (tid < 64) { Bs[tid] = g_eb1f[tid]; Bs[64 + tid] = eb2[tid]; }
    else if (tid < 96) Bs[128 + tid - 64] = eb3[tid - 64];

    // ---- stage X: 64 rows x 3 segments (a1 | a2 | bond), quarter 3 idle ----
    {
        const int m = tid >> 2, q = tid & 3;
        if (q < 3) {
            const int gid = base + m;
            const int wbase = m * 52 + q * 16;
            if (q < 2) {
                // gathered atom rows: pre-split fp16, pure copy
                int a = (q == 0) ? ba1[gid] : ba2[gid];
                if (q == 0) { A1s[m] = a; atomicAdd(&g_cnt[a], 1.0f); }
                const int4* sh = (const int4*)(g_ath + (size_t)a * 32);
                const int4* sl = (const int4*)(g_atl + (size_t)a * 32);
#pragma unroll
                for (int p = 0; p < 4; p++) {
                    ((int4*)(Xh + wbase))[p] = sh[p];
                    ((int4*)(Xl + wbase))[p] = sl[p];
                }
            } else {
                const float* src = bonds + (size_t)gid * 32;
#pragma unroll
                for (int p = 0; p < 8; p++) {
                    float4 v = *(const float4*)(src + 4 * p);
                    uint32_t hw, lw;
                    split_pair(v.x, v.y, hw, lw);
                    Xh[wbase + 2 * p] = hw; Xl[wbase + 2 * p] = lw;
                    split_pair(v.z, v.w, hw, lw);
                    Xh[wbase + 2 * p + 1] = hw; Xl[wbase + 2 * p + 1] = lw;
                }
            }
        }
    }
    CP_WAIT0();
    __syncthreads();

    // lane-resolved fragment offsets
    const uint32_t a_loc = (uint32_t)(lane & 15);          // local row in pair
    const uint32_t a_kb  = (uint32_t)((lane >> 4) << 4);
    const uint32_t b_row = (uint32_t)(((lane >> 4) << 3) + (lane & 7));
    const uint32_t b_kb  = (uint32_t)(((lane >> 3) & 1) << 4);
    const uint32_t hb_h  = sb + B_XB + (uint32_t)wm * 3328;          // pair H hi base
    const uint32_t hb_l  = sb + B_XB + 13312 + (uint32_t)wm * 3328;  // pair H lo base

    // ---- layer 1: K=96 (X stride 208B), W1 stride 208B ----
    {
        float acc[4][4];
        uint32_t ao = ((uint32_t)(wm * 16) + a_loc) * 208 + a_kb;
        uint32_t bo = (wn * 32 + b_row) * 208 + b_kb;
        mlp_layer<6, 4, true>(sb + B_XB + ao, sb + B_XB + 13312 + ao,
                              sb + B_WB + bo, 208, acc);
        PAIR_BAR(wm);  // pair done reading its X rows
        epi_to_h<4>(acc, Bs, Hh, Hl, wn, g, t);
    }
    PAIR_BAR(wm);

    // ---- layer 2: K=64 (H stride 144B), W2 stride 144B ----
    {
        float acc[4][4];
        uint32_t ao = a_loc * 144 + a_kb;
        uint32_t bo = (wn * 32 + b_row) * 144 + b_kb;
        mlp_layer<4, 4, true>(hb_h + ao, hb_l + ao,
                              sb + B_WB + 13312 + bo, 144, acc);
        PAIR_BAR(wm);  // pair done reading H1
        epi_to_h<4>(acc, Bs + 64, Hh, Hl, wn, g, t);
    }
    PAIR_BAR(wm);

    // ---- layer 3: K=64, N=32 (single-pass hi) ----
    {
        float acc[2][4];
        uint32_t ao = a_loc * 144 + a_kb;
        uint32_t bo = (wn * 16 + b_row) * 144 + b_kb;
        mlp_layer<4, 2, false>(hb_h + ao, hb_l + ao,
                               sb + B_WB + 22528 + bo, 144, acc);
        epi_to_f32(acc, Bs + 128, H3, wm, wn, g, t);
    }
    __syncthreads();

    // ---- outputs ----
    for (int idx = tid; idx < TMROWS * 8; idx += NT) {
        int r = idx >> 3, f4 = idx & 7;
        float4 v = *(float4*)&H3[r * 36 + (f4 << 2)];
        *(float4*)&out_bonds[(size_t)(base + r) * 32 + (f4 << 2)] = v;
    }
    for (int r = wid; r < TMROWS; r += 8)
        atomicAdd(&g_b2a[(size_t)A1s[r] * 32 + lane], H3[r * 36 + lane]);
    if (tid < 32) {
        float ssum = 0.f;
        for (int r = 0; r < TMROWS; r++) ssum += H3[r * 36 + tid];
        atomicAdd(&g_bsum[tid], ssum);
    }
}

// ================= phi_v over atoms =================
__global__ void __launch_bounds__(NT, 3) atom_kernel(
    const float* __restrict__ vb2, const float* __restrict__ vb3,
    float* __restrict__ out_atoms, int n_atoms)
{
    extern __shared__ char smem[];
    const uint32_t sb = smem_u32(smem);
    const int tid  = threadIdx.x;
    const int wid  = tid >> 5;
    const int lane = tid & 31;
    const int g = lane >> 2, t = lane & 3;
    const int wm = wid >> 1, wn = wid & 1;
    const int base = blockIdx.x * TMROWS;

    float* Bs = (float*)(smem + A_BIAS);
    uint32_t* Xh = (uint32_t*)(smem + A_XB);
    uint32_t* Xl = (uint32_t*)(smem + A_XB + 9216);
    uint32_t* Hh = Xh + wm * 576;   // pair X range = 16*36 = 576 words (exact H fit)
    uint32_t* Hl = Xl + wm * 576;
    float*    H3 = (float*)(smem + A_XB + 18432);

    for (int i = tid; i < 23040 / 16; i += NT)
        cp16(sb + A_WB + i * 16, (const char*)g_wv + i * 16);
    CP_COMMIT();
    if (tid < 64) { Bs[tid] = g_vb1f[tid]; Bs[64 + tid] = vb2[tid]; }
    else if (tid < 96) Bs[128 + tid - 64] = vb3[tid - 64];

    // ---- stage X: 64 rows x 2 segments (b2a | atoms); tid<128 active ----
    if (tid < 128) {
        const int m = tid >> 1, q = tid & 1;
        const int gm = base + m;
        const int id = gm < n_atoms ? gm : n_atoms - 1;
        const int wbase = m * 36 + q * 16;
        if (q == 0) {
            float inv = 1.0f / g_cnt[id];
#pragma unroll
            for (int p = 0; p < 8; p++) {
                float4 v = *(const float4*)&g_b2a[(size_t)id * 32 + 4 * p];
                uint32_t hw, lw;
                split_pair(v.x * inv, v.y * inv, hw, lw);
                Xh[wbase + 2 * p] = hw; Xl[wbase + 2 * p] = lw;
                split_pair(v.z * inv, v.w * inv, hw, lw);
                Xh[wbase + 2 * p + 1] = hw; Xl[wbase + 2 * p + 1] = lw;
            }
        } else {
            // atoms segment: pre-split fp16, pure copy
            const int4* sh = (const int4*)(g_ath + (size_t)id * 32);
            const int4* sl = (const int4*)(g_atl + (size_t)id * 32);
#pragma unroll
            for (int p = 0; p < 4; p++) {
                ((int4*)(Xh + wbase))[p] = sh[p];
                ((int4*)(Xl + wbase))[p] = sl[p];
            }
        }
    }
    CP_WAIT0();
    __syncthreads();

    const uint32_t a_loc = (uint32_t)(lane & 15);
    const uint32_t a_kb  = (uint32_t)((lane >> 4) << 4);
    const uint32_t b_row = (uint32_t)(((lane >> 4) << 3) + (lane & 7));
    const uint32_t b_kb  = (uint32_t)(((lane >> 3) & 1) << 4);
    const uint32_t hb_h  = sb + A_XB + (uint32_t)wm * 2304;
    const uint32_t hb_l  = sb + A_XB + 9216 + (uint32_t)wm * 2304;

    // ---- layer 1: K=64 (X stride 144B), V1 stride 144B ----
    {
        float acc[4][4];
        uint32_t ao = ((uint32_t)(wm * 16) + a_loc) * 144 + a_kb;
        uint32_t bo = (wn * 32 + b_row) * 144 + b_kb;
        mlp_layer<4, 4, true>(sb + A_XB + ao, sb + A_XB + 9216 + ao,
                              sb + A_WB + bo, 144, acc);
        PAIR_BAR(wm);
        epi_to_h<4>(acc, Bs, Hh, Hl, wn, g, t);
    }
    PAIR_BAR(wm);

    // ---- layer 2 ----
    {
        float acc[4][4];
        uint32_t ao = a_loc * 144 + a_kb;
        uint32_t bo = (wn * 32 + b_row) * 144 + b_kb;
        mlp_layer<4, 4, true>(hb_h + ao, hb_l + ao,
                              sb + A_WB + 9216 + bo, 144, acc);
        PAIR_BAR(wm);
        epi_to_h<4>(acc, Bs + 64, Hh, Hl, wn, g, t);
    }
    PAIR_BAR(wm);

    // ---- layer 3 (single-pass hi) ----
    {
        float acc[2][4];
        uint32_t ao = a_loc * 144 + a_kb;
        uint32_t bo = (wn * 16 + b_row) * 144 + b_kb;
        mlp_layer<4, 2, false>(hb_h + ao, hb_l + ao,
                               sb + A_WB + 18432 + bo, 144, acc);
        epi_to_f32(acc, Bs + 128, H3, wm, wn, g, t);
    }
    __syncthreads();

    for (int idx = tid; idx < TMROWS * 8; idx += NT) {
        int r = idx >> 3, f4 = idx & 7;
        if (base + r < n_atoms) {
            float4 v = *(float4*)&H3[r * 36 + (f4 << 2)];
            *(float4*)&out_atoms[(size_t)(base + r) * 32 + (f4 << 2)] = v;
        }
    }
    if (tid < 32) {
        float ssum = 0.f;
        for (int r = 0; r < TMROWS; r++)
            if (base + r < n_atoms) ssum += H3[r * 36 + tid];
        atomicAdd(&g_asum[tid], ssum);
    }
}

// ================= phi_u =================
__global__ void state_kernel(
    const float* __restrict__ state,
    const float* __restrict__ uw1, const float* __restrict__ ub1,
    const float* __restrict__ uw2, const float* __restrict__ ub2,
    const float* __restrict__ uw3, const float* __restrict__ ub3,
    float* __restrict__ out_state, int n_bonds, int n_atoms)
{
    __shared__ float x[96], h1[64], h2[64];
    int tid = threadIdx.x;  // 64 threads
    if (tid < 32) {
        x[tid]      = g_bsum[tid] / (float)n_bonds;
        x[32 + tid] = g_asum[tid] / (float)n_atoms;
        x[64 + tid] = state[tid];
    }
    __syncthreads();
    {
        float a = ub1[tid];
        for (int k = 0; k < 96; k++) a = fmaf(x[k], uw1[k * 64 + tid], a);
        h1[tid] = selu_f(a);
    }
    __syncthreads();
    {
        float a = ub2[tid];
        for (int k = 0; k < 64; k++) a = fmaf(h1[k], uw2[k * 64 + tid], a);
        h2[tid] = selu_f(a);
    }
    __syncthreads();
    if (tid < 32) {
        float a = ub3[tid];
        for (int k = 0; k < 64; k++) a = fmaf(h2[k], uw3[k * 32 + tid], a);
        out_state[tid] = selu_f(a);
    }
}

// ================= launch =================
extern "C" void kernel_launch(void* const* d_in, const int* in_sizes, int n_in,
                              void* d_out, int out_size)
{
    const float* bonds = (const float*)d_in[0];
    const int*   ba1   = (const int*)d_in[1];
    const int*   ba2   = (const int*)d_in[2];
    const float* atoms = (const float*)d_in[3];
    const float* state = (const float*)d_in[4];
    const float* ew1 = (const float*)d_in[5];
    const float* eb1 = (const float*)d_in[6];
    const float* ew2 = (const float*)d_in[7];
    const float* eb2 = (const float*)d_in[8];
    const float* ew3 = (const float*)d_in[9];
    const float* eb3 = (const float*)d_in[10];
    const float* vw1 = (const float*)d_in[11];
    const float* vb1 = (const float*)d_in[12];
    const float* vw2 = (const float*)d_in[13];
    const float* vb2 = (const float*)d_in[14];
    const float* vw3 = (const float*)d_in[15];
    const float* vb3 = (const float*)d_in[16];
    const float* uw1 = (const float*)d_in[17];
    const float* ub1 = (const float*)d_in[18];
    const float* uw2 = (const float*)d_in[19];
    const float* ub2 = (const float*)d_in[20];
    const float* uw3 = (const float*)d_in[21];
    const float* ub3 = (const float*)d_in[22];

    const int n_bonds = in_sizes[1];
    const int n_atoms = in_sizes[3] / 32;

    float* out       = (float*)d_out;
    float* out_bonds = out;
    float* out_atoms = out + (size_t)n_bonds * 32;
    float* out_state = out_atoms + (size_t)n_atoms * 32;

    cudaFuncSetAttribute(bond_kernel, cudaFuncAttributeMaxDynamicSharedMemorySize, B_SMEM);
    cudaFuncSetAttribute(atom_kernel, cudaFuncAttributeMaxDynamicSharedMemorySize, A_SMEM);

    zero_kernel<<<256, 256>>>(atoms, n_atoms);
    prep_kernel<<<(25216 + 255) / 256, 256>>>(ew1, ew2, ew3, vw1, vw2, vw3,
                                              eb1, vb1, state);

    int bond_blocks = n_bonds / TMROWS;
    bond_kernel<<<bond_blocks, NT, B_SMEM>>>(
        bonds, ba1, ba2, eb2, eb3, out_bonds, n_bonds);

    int atom_blocks = (n_atoms + TMROWS - 1) / TMROWS;
    atom_kernel<<<atom_blocks, NT, A_SMEM>>>(
        vb2, vb3, out_atoms, n_atoms);

    state_kernel<<<1, 64>>>(state, uw1, ub1, uw2, ub2, uw3, ub3,
                            out_state, n_bonds, n_atoms);
}

// round 16
// speedup vs baseline: 1.7165x; 1.0517x over previous
#include <cuda_runtime.h>
#include <cuda_fp16.h>
#include <math.h>
#include <stdint.h>

// ================= scratch (no allocations allowed) =================
#define MAX_ATOMS 100000
__device__ float g_b2a[MAX_ATOMS * 32];
__device__ float g_cnt[MAX_ATOMS];
__device__ float g_bsum[32];
__device__ float g_asum[32];
__device__ float g_eb1f[64];   // fused bias: eb1 + state @ ew1[96:128]
__device__ float g_vb1f[64];   // fused bias: vb1 + state @ vw1[64:96]
// pre-split fp16 hi/lo images of the atoms table (L2-resident, built once)
__device__ __align__(16) __half g_ath[MAX_ATOMS * 32];
__device__ __align__(16) __half g_atl[MAX_ATOMS * 32];

// pre-transposed fp16 weight images Wt[n][k], padded k-stride
__device__ __align__(16) __half g_we[13568];  // W1(64x104)@0 W2(64x72)@6656 W3(32x72)@11264
__device__ __align__(16) __half g_wv[11520];  // V1(64x72)@0  V2(64x72)@4608 V3(32x72)@9216

__device__ __forceinline__ float selu_f(float x) {
    const float lam = 1.0507009873554805f;
    const float la  = 1.7580993408473766f;
    float e = __expf(x);
    return x > 0.f ? lam * x : fmaf(la, e, -la);
}

// fp32 pair -> fp16x2 hi word + fp16x2 residual word (packed cvt)
__device__ __forceinline__ void split_pair(float v0, float v1, uint32_t& hw, uint32_t& lw) {
    __half2 hp = __floats2half2_rn(v0, v1);
    float2 hf = __half22float2(hp);
    __half2 lp = __floats2half2_rn(v0 - hf.x, v1 - hf.y);
    hw = *(uint32_t*)&hp;
    lw = *(uint32_t*)&lp;
}
// fp32 pair -> fp16x2 hi word only
__device__ __forceinline__ uint32_t pack_hi(float v0, float v1) {
    __half2 hp = __floats2half2_rn(v0, v1);
    return *(uint32_t*)&hp;
}

__device__ __forceinline__ uint32_t smem_u32(const void* p) {
    uint32_t a;
    asm("{ .reg .u64 t; cvta.to.shared.u64 t, %1; cvt.u32.u64 %0, t; }" : "=r"(a) : "l"(p));
    return a;
}

// ---- baseline-ISA ops (valid on plain sm_100) ----
__device__ __forceinline__ void ldmx4(uint32_t r[4], uint32_t addr) {
    asm volatile("ldmatrix.sync.aligned.m8n8.x4.shared.b16 {%0,%1,%2,%3}, [%4];"
        : "=r"(r[0]), "=r"(r[1]), "=r"(r[2]), "=r"(r[3]) : "r"(addr));
}
__device__ __forceinline__ void mma_f16(float c[4], const uint32_t a[4], uint32_t b0, uint32_t b1) {
    asm("mma.sync.aligned.m16n8k16.row.col.f32.f16.f16.f32 "
        "{%0,%1,%2,%3}, {%4,%5,%6,%7}, {%8,%9}, {%0,%1,%2,%3};"
        : "+f"(c[0]), "+f"(c[1]), "+f"(c[2]), "+f"(c[3])
        : "r"(a[0]), "r"(a[1]), "r"(a[2]), "r"(a[3]), "r"(b0), "r"(b1));
}
__device__ __forceinline__ void cp16(uint32_t dst, const void* src) {
    asm volatile("cp.async.ca.shared.global [%0], [%1], 16;" :: "r"(dst), "l"(src));
}
#define CP_COMMIT() asm volatile("cp.async.commit_group;" ::: "memory")
#define CP_WAIT0()  asm volatile("cp.async.wait_group 0;" ::: "memory")
// pair-scoped barrier: 2 warps (64 threads), ids 1..4
#define PAIR_BAR(wm) asm volatile("bar.sync %0, 64;" :: "r"((wm) + 1) : "memory")

// dense layer: acc[NTW][4] += A(16 rows x K) @ Wt^T  (fp16, TWO=2-pass hi+lo)
template <int KS, int NTW, bool TWO>
__device__ __forceinline__ void mlp_layer(
    uint32_t xh_addr, uint32_t xl_addr,
    uint32_t b_addr, uint32_t sbwB,
    float acc[NTW][4])
{
#pragma unroll
    for (int j = 0; j < NTW; j++)
#pragma unroll
        for (int q = 0; q < 4; q++) acc[j][q] = 0.f;

#pragma unroll
    for (int k = 0; k < KS; k++) {
        uint32_t ah[4], al[4];
        ldmx4(ah, xh_addr);
        if (TWO) ldmx4(al, xl_addr);
        xh_addr += 32; xl_addr += 32;
#pragma unroll
        for (int p = 0; p < NTW / 2; p++) {
            uint32_t rw[4];
            ldmx4(rw, b_addr + p * 8 * sbwB * 2);
            mma_f16(acc[2 * p],     ah, rw[0], rw[1]);
            mma_f16(acc[2 * p + 1], ah, rw[2], rw[3]);
            if (TWO) {
                mma_f16(acc[2 * p],     al, rw[0], rw[1]);
                mma_f16(acc[2 * p + 1], al, rw[2], rw[3]);
            }
        }
        b_addr += 32;
    }
}

// epilogue: bias+selu -> fp16 hi-only pair-LOCAL H image (rows 0..15, stride 36 words)
template <int NTW>
__device__ __forceinline__ void epi_to_h_hi(
    float acc[NTW][4], const float* bias,
    uint32_t* Hh, int wn, int g, int t)
{
    const int r0 = g;  // local row within pair
#pragma unroll
    for (int j = 0; j < NTW; j++) {
        int col = wn * 32 + j * 8 + 2 * t;
        int cw  = wn * 16 + j * 4 + t;
        float b0 = bias[col], b1 = bias[col + 1];
        Hh[r0 * 36 + cw]       = pack_hi(selu_f(acc[j][0] + b0), selu_f(acc[j][1] + b1));
        Hh[(r0 + 8) * 36 + cw] = pack_hi(selu_f(acc[j][2] + b0), selu_f(acc[j][3] + b1));
    }
}

// epilogue: bias+selu -> fp32 H3 [64][36] (global rows), N=32
__device__ __forceinline__ void epi_to_f32(
    float acc[2][4], const float* bias, float* H3, int wm, int wn, int g, int t)
{
    const int r0 = wm * 16 + g;
#pragma unroll
    for (int j = 0; j < 2; j++) {
        int col = wn * 16 + j * 8 + 2 * t;
        float b0 = bias[col], b1 = bias[col + 1];
        float2 v;
        v.x = selu_f(acc[j][0] + b0);
        v.y = selu_f(acc[j][1] + b1);
        *(float2*)&H3[r0 * 36 + col] = v;
        v.x = selu_f(acc[j][2] + b0);
        v.y = selu_f(acc[j][3] + b1);
        *(float2*)&H3[(r0 + 8) * 36 + col] = v;
    }
}

// ================= zero scratch + atoms pre-split =================
__global__ void zero_kernel(const float* __restrict__ atoms, int n_atoms)
{
    int i = blockIdx.x * blockDim.x + threadIdx.x;
    int stride = gridDim.x * blockDim.x;
    int nb = n_atoms * 32;
    for (int idx = i; idx < nb; idx += stride) {
        g_b2a[idx] = 0.f;
        float v = atoms[idx];
        __half h = __float2half(v);
        g_ath[idx] = h;
        g_atl[idx] = __float2half(v - __half2float(h));
    }
    for (int idx = i; idx < n_atoms; idx += stride) g_cnt[idx] = 0.f;
    if (i < 32) { g_bsum[i] = 0.f; g_asum[i] = 0.f; }
}

// ================= weight transpose prep + state-bias fold =================
__global__ void prep_kernel(
    const float* __restrict__ ew1, const float* __restrict__ ew2, const float* __restrict__ ew3,
    const float* __restrict__ vw1, const float* __restrict__ vw2, const float* __restrict__ vw3,
    const float* __restrict__ eb1, const float* __restrict__ vb1,
    const float* __restrict__ state)
{
    int i = blockIdx.x * blockDim.x + threadIdx.x;
    if (i < 25088) {
        const float* src; __half* img;
        int stride, N, Ksrc, local;
        if (i < 6656)        { local = i;         stride = 104; N = 64; Ksrc = 96; src = ew1; img = g_we; }
        else if (i < 11264)  { local = i - 6656;  stride = 72;  N = 64; Ksrc = 64; src = ew2; img = g_we + 6656; }
        else if (i < 13568)  { local = i - 11264; stride = 72;  N = 32; Ksrc = 64; src = ew3; img = g_we + 11264; }
        else if (i < 18176)  { local = i - 13568; stride = 72;  N = 64; Ksrc = 64; src = vw1; img = g_wv; }
        else if (i < 22784)  { local = i - 18176; stride = 72;  N = 64; Ksrc = 64; src = vw2; img = g_wv + 4608; }
        else                 { local = i - 22784; stride = 72;  N = 32; Ksrc = 64; src = vw3; img = g_wv + 9216; }
        int n = local / stride, k = local % stride;
        float w = (k < Ksrc) ? src[k * N + n] : 0.f;
        img[local] = __float2half(w);
    } else if (i < 25216) {
        int n = i - 25088;
        if (n < 64) {
            float a = eb1[n];
            for (int j = 0; j < 32; j++) a = fmaf(state[j], ew1[(96 + j) * 64 + n], a);
            g_eb1f[n] = a;
        } else {
            n -= 64;
            float a = vb1[n];
            for (int j = 0; j < 32; j++) a = fmaf(state[j], vw1[(64 + j) * 64 + n], a);
            g_vb1f[n] = a;
        }
    }
}

// ================= smem maps (bytes) =================
// bond: Xh 13312 + Xl 13312 (K=96, stride 208B); pair H (hi only) overlays own Xh range
// H3 @ B_XB+26624 (9216); weights @ B_XB+35840: W1 13312, W2 @+13312, W3 @+22528
#define B_BIAS   0
#define B_A1S    640
#define B_XB     1024
#define B_WB     36864
#define B_SMEM   64000
// atom: Xh 9216 + Xl 9216 (K=64, stride 144B); pair H (hi only) = pair Xh exactly
// H3 @ A_XB+18432 (9216); weights @ A_XB+27648: V1 9216, V2 @+9216, V3 @+18432
#define A_BIAS   0
#define A_XB     768
#define A_WB     28416
#define A_SMEM   51456

#define NT 256
#define TMROWS 64

// ================= phi_e over bonds =================
__global__ void __launch_bounds__(NT, 3) bond_kernel(
    const float* __restrict__ bonds, const int* __restrict__ ba1,
    const int* __restrict__ ba2,
    const float* __restrict__ eb2, const float* __restrict__ eb3,
    float* __restrict__ out_bonds, int n_bonds)
{
    extern __shared__ char smem[];
    const uint32_t sb = smem_u32(smem);
    const int tid  = threadIdx.x;
    const int wid  = tid >> 5;
    const int lane = tid & 31;
    const int g = lane >> 2, t = lane & 3;
    const int wm = wid >> 1, wn = wid & 1;   // 4 pairs x 2 n-warps
    const int base = blockIdx.x * TMROWS;

    float* Bs  = (float*)(smem + B_BIAS);
    int*   A1s = (int*)(smem + B_A1S);
    uint32_t* Xh = (uint32_t*)(smem + B_XB);
    uint32_t* Xl = (uint32_t*)(smem + B_XB + 13312);
    // pair-local H hi (inside own Xh range: 832 words/pair >= 576 needed)
    uint32_t* Hh = Xh + wm * 832;
    float*    H3 = (float*)(smem + B_XB + 26624);

    // weights -> smem (cp.async), 27136 B
    for (int i = tid; i < 27136 / 16; i += NT)
        cp16(sb + B_WB + i * 16, (const char*)g_we + i * 16);
    CP_COMMIT();
    if (tid < 64) { Bs[tid] = g_eb1f[tid]; Bs[64 + tid] = eb2[tid]; }
    else if (tid < 96) Bs[128 + tid - 64] = eb3[tid - 64];

    // ---- stage X: 64 rows x 3 segments (a1 | a2 | bond), quarter 3 idle ----
    {
        const int m = tid >> 2, q = tid & 3;
        if (q < 3) {
            const int gid = base + m;
            const int wbase = m * 52 + q * 16;
            if (q < 2) {
                int a = (q == 0) ? ba1[gid] : ba2[gid];
                if (q == 0) { A1s[m] = a; atomicAdd(&g_cnt[a], 1.0f); }
                const int4* sh = (const int4*)(g_ath + (size_t)a * 32);
                const int4* sl = (const int4*)(g_atl + (size_t)a * 32);
#pragma unroll
                for (int p = 0; p < 4; p++) {
                    ((int4*)(Xh + wbase))[p] = sh[p];
                    ((int4*)(Xl + wbase))[p] = sl[p];
                }
            } else {
                const float* src = bonds + (size_t)gid * 32;
#pragma unroll
                for (int p = 0; p < 8; p++) {
                    float4 v = *(const float4*)(src + 4 * p);
                    uint32_t hw, lw;
                    split_pair(v.x, v.y, hw, lw);
                    Xh[wbase + 2 * p] = hw; Xl[wbase + 2 * p] = lw;
                    split_pair(v.z, v.w, hw, lw);
                    Xh[wbase + 2 * p + 1] = hw; Xl[wbase + 2 * p + 1] = lw;
                }
            }
        }
    }
    CP_WAIT0();
    __syncthreads();

    // lane-resolved fragment offsets
    const uint32_t a_loc = (uint32_t)(lane & 15);          // local row in pair
    const uint32_t a_kb  = (uint32_t)((lane >> 4) << 4);
    const uint32_t b_row = (uint32_t)(((lane >> 4) << 3) + (lane & 7));
    const uint32_t b_kb  = (uint32_t)(((lane >> 3) & 1) << 4);
    const uint32_t hb_h  = sb + B_XB + (uint32_t)wm * 3328;  // pair H hi base

    // ---- layer 1: K=96 (X stride 208B), W1 stride 208B, 2-pass ----
    {
        float acc[4][4];
        uint32_t ao = ((uint32_t)(wm * 16) + a_loc) * 208 + a_kb;
        uint32_t bo = (wn * 32 + b_row) * 208 + b_kb;
        mlp_layer<6, 4, true>(sb + B_XB + ao, sb + B_XB + 13312 + ao,
                              sb + B_WB + bo, 208, acc);
        PAIR_BAR(wm);  // pair done reading its X rows
        epi_to_h_hi<4>(acc, Bs, Hh, wn, g, t);
    }
    PAIR_BAR(wm);

    // ---- layer 2: K=64 (H stride 144B), W2 stride 144B, single-pass ----
    {
        float acc[4][4];
        uint32_t ao = a_loc * 144 + a_kb;
        uint32_t bo = (wn * 32 + b_row) * 144 + b_kb;
        mlp_layer<4, 4, false>(hb_h + ao, 0,
                               sb + B_WB + 13312 + bo, 144, acc);
        PAIR_BAR(wm);  // pair done reading H1
        epi_to_h_hi<4>(acc, Bs + 64, Hh, wn, g, t);
    }
    PAIR_BAR(wm);

    // ---- layer 3: K=64, N=32, single-pass ----
    {
        float acc[2][4];
        uint32_t ao = a_loc * 144 + a_kb;
        uint32_t bo = (wn * 16 + b_row) * 144 + b_kb;
        mlp_layer<4, 2, false>(hb_h + ao, 0,
                               sb + B_WB + 22528 + bo, 144, acc);
        epi_to_f32(acc, Bs + 128, H3, wm, wn, g, t);
    }
    __syncthreads();

    // ---- outputs ----
    for (int idx = tid; idx < TMROWS * 8; idx += NT) {
        int r = idx >> 3, f4 = idx & 7;
        float4 v = *(float4*)&H3[r * 36 + (f4 << 2)];
        *(float4*)&out_bonds[(size_t)(base + r) * 32 + (f4 << 2)] = v;
    }
    for (int r = wid; r < TMROWS; r += 8)
        atomicAdd(&g_b2a[(size_t)A1s[r] * 32 + lane], H3[r * 36 + lane]);
    if (tid < 32) {
        float ssum = 0.f;
        for (int r = 0; r < TMROWS; r++) ssum += H3[r * 36 + tid];
        atomicAdd(&g_bsum[tid], ssum);
    }
}

// ================= phi_v over atoms =================
__global__ void __launch_bounds__(NT, 3) atom_kernel(
    const float* __restrict__ vb2, const float* __restrict__ vb3,
    float* __restrict__ out_atoms, int n_atoms)
{
    extern __shared__ char smem[];
    const uint32_t sb = smem_u32(smem);
    const int tid  = threadIdx.x;
    const int wid  = tid >> 5;
    const int lane = tid & 31;
    const int g = lane >> 2, t = lane & 3;
    const int wm = wid >> 1, wn = wid & 1;
    const int base = blockIdx.x * TMROWS;

    float* Bs = (float*)(smem + A_BIAS);
    uint32_t* Xh = (uint32_t*)(smem + A_XB);
    uint32_t* Xl = (uint32_t*)(smem + A_XB + 9216);
    uint32_t* Hh = Xh + wm * 576;   // pair X range = 16*36 = 576 words (exact H fit)
    float*    H3 = (float*)(smem + A_XB + 18432);

    for (int i = tid; i < 23040 / 16; i += NT)
        cp16(sb + A_WB + i * 16, (const char*)g_wv + i * 16);
    CP_COMMIT();
    if (tid < 64) { Bs[tid] = g_vb1f[tid]; Bs[64 + tid] = vb2[tid]; }
    else if (tid < 96) Bs[128 + tid - 64] = vb3[tid - 64];

    // ---- stage X: 64 rows x 2 segments (b2a | atoms); tid<128 active ----
    if (tid < 128) {
        const int m = tid >> 1, q = tid & 1;
        const int gm = base + m;
        const int id = gm < n_atoms ? gm : n_atoms - 1;
        const int wbase = m * 36 + q * 16;
        if (q == 0) {
            float inv = 1.0f / g_cnt[id];
#pragma unroll
            for (int p = 0; p < 8; p++) {
                float4 v = *(const float4*)&g_b2a[(size_t)id * 32 + 4 * p];
                uint32_t hw, lw;
                split_pair(v.x * inv, v.y * inv, hw, lw);
                Xh[wbase + 2 * p] = hw; Xl[wbase + 2 * p] = lw;
                split_pair(v.z * inv, v.w * inv, hw, lw);
                Xh[wbase + 2 * p + 1] = hw; Xl[wbase + 2 * p + 1] = lw;
            }
        } else {
            const int4* sh = (const int4*)(g_ath + (size_t)id * 32);
            const int4* sl = (const int4*)(g_atl + (size_t)id * 32);
#pragma unroll
            for (int p = 0; p < 4; p++) {
                ((int4*)(Xh + wbase))[p] = sh[p];
                ((int4*)(Xl + wbase))[p] = sl[p];
            }
        }
    }
    CP_WAIT0();
    __syncthreads();

    const uint32_t a_loc = (uint32_t)(lane & 15);
    const uint32_t a_kb  = (uint32_t)((lane >> 4) << 4);
    const uint32_t b_row = (uint32_t)(((lane >> 4) << 3) + (lane & 7));
    const uint32_t b_kb  = (uint32_t)(((lane >> 3) & 1) << 4);
    const uint32_t hb_h  = sb + A_XB + (uint32_t)wm * 2304;

    // ---- layer 1: K=64 (X stride 144B), V1 stride 144B, 2-pass ----
    {
        float acc[4][4];
        uint32_t ao = ((uint32_t)(wm * 16) + a_loc) * 144 + a_kb;
        uint32_t bo = (wn * 32 + b_row) * 144 + b_kb;
        mlp_layer<4, 4, true>(sb + A_XB + ao, sb + A_XB + 9216 + ao,
                              sb + A_WB + bo, 144, acc);
        PAIR_BAR(wm);
        epi_to_h_hi<4>(acc, Bs, Hh, wn, g, t);
    }
    PAIR_BAR(wm);

    // ---- layer 2: single-pass ----
    {
        float acc[4][4];
        uint32_t ao = a_loc * 144 + a_kb;
        uint32_t bo = (wn * 32 + b_row) * 144 + b_kb;
        mlp_layer<4, 4, false>(hb_h + ao, 0,
                               sb + A_WB + 9216 + bo, 144, acc);
        PAIR_BAR(wm);
        epi_to_h_hi<4>(acc, Bs + 64, Hh, wn, g, t);
    }
    PAIR_BAR(wm);

    // ---- layer 3: single-pass ----
    {
        float acc[2][4];
        uint32_t ao = a_loc * 144 + a_kb;
        uint32_t bo = (wn * 16 + b_row) * 144 + b_kb;
        mlp_layer<4, 2, false>(hb_h + ao, 0,
                               sb + A_WB + 18432 + bo, 144, acc);
        epi_to_f32(acc, Bs + 128, H3, wm, wn, g, t);
    }
    __syncthreads();

    for (int idx = tid; idx < TMROWS * 8; idx += NT) {
        int r = idx >> 3, f4 = idx & 7;
        if (base + r < n_atoms) {
            float4 v = *(float4*)&H3[r * 36 + (f4 << 2)];
            *(float4*)&out_atoms[(size_t)(base + r) * 32 + (f4 << 2)] = v;
        }
    }
    if (tid < 32) {
        float ssum = 0.f;
        for (int r = 0; r < TMROWS; r++)
            if (base + r < n_atoms) ssum += H3[r * 36 + tid];
        atomicAdd(&g_asum[tid], ssum);
    }
}

// ================= phi_u =================
__global__ void state_kernel(
    const float* __restrict__ state,
    const float* __restrict__ uw1, const float* __restrict__ ub1,
    const float* __restrict__ uw2, const float* __restrict__ ub2,
    const float* __restrict__ uw3, const float* __restrict__ ub3,
    float* __restrict__ out_state, int n_bonds, int n_atoms)
{
    __shared__ float x[96], h1[64], h2[64];
    int tid = threadIdx.x;  // 64 threads
    if (tid < 32) {
        x[tid]      = g_bsum[tid] / (float)n_bonds;
        x[32 + tid] = g_asum[tid] / (float)n_atoms;
        x[64 + tid] = state[tid];
    }
    __syncthreads();
    {
        float a = ub1[tid];
        for (int k = 0; k < 96; k++) a = fmaf(x[k], uw1[k * 64 + tid], a);
        h1[tid] = selu_f(a);
    }
    __syncthreads();
    {
        float a = ub2[tid];
        for (int k = 0; k < 64; k++) a = fmaf(h1[k], uw2[k * 64 + tid], a);
        h2[tid] = selu_f(a);
    }
    __syncthreads();
    if (tid < 32) {
        float a = ub3[tid];
        for (int k = 0; k < 64; k++) a = fmaf(h2[k], uw3[k * 32 + tid], a);
        out_state[tid] = selu_f(a);
    }
}

// ================= launch =================
extern "C" void kernel_launch(void* const* d_in, const int* in_sizes, int n_in,
                              void* d_out, int out_size)
{
    const float* bonds = (const float*)d_in[0];
    const int*   ba1   = (const int*)d_in[1];
    const int*   ba2   = (const int*)d_in[2];
    const float* atoms = (const float*)d_in[3];
    const float* state = (const float*)d_in[4];
    const float* ew1 = (const float*)d_in[5];
    const float* eb1 = (const float*)d_in[6];
    const float* ew2 = (const float*)d_in[7];
    const float* eb2 = (const float*)d_in[8];
    const float* ew3 = (const float*)d_in[9];
    const float* eb3 = (const float*)d_in[10];
    const float* vw1 = (const float*)d_in[11];
    const float* vb1 = (const float*)d_in[12];
    const float* vw2 = (const float*)d_in[13];
    const float* vb2 = (const float*)d_in[14];
    const float* vw3 = (const float*)d_in[15];
    const float* vb3 = (const float*)d_in[16];
    const float* uw1 = (const float*)d_in[17];
    const float* ub1 = (const float*)d_in[18];
    const float* uw2 = (const float*)d_in[19];
    const float* ub2 = (const float*)d_in[20];
    const float* uw3 = (const float*)d_in[21];
    const float* ub3 = (const float*)d_in[22];

    const int n_bonds = in_sizes[1];
    const int n_atoms = in_sizes[3] / 32;

    float* out       = (float*)d_out;
    float* out_bonds = out;
    float* out_atoms = out + (size_t)n_bonds * 32;
    float* out_state = out_atoms + (size_t)n_atoms * 32;

    cudaFuncSetAttribute(bond_kernel, cudaFuncAttributeMaxDynamicSharedMemorySize, B_SMEM);
    cudaFuncSetAttribute(atom_kernel, cudaFuncAttributeMaxDynamicSharedMemorySize, A_SMEM);

    zero_kernel<<<256, 256>>>(atoms, n_atoms);
    prep_kernel<<<(25216 + 255) / 256, 256>>>(ew1, ew2, ew3, vw1, vw2, vw3,
                                              eb1, vb1, state);

    int bond_blocks = n_bonds / TMROWS;
    bond_kernel<<<bond_blocks, NT, B_SMEM>>>(
        bonds, ba1, ba2, eb2, eb3, out_bonds, n_bonds);

    int atom_blocks = (n_atoms + TMROWS - 1) / TMROWS;
    atom_kernel<<<atom_blocks, NT, A_SMEM>>>(
        vb2, vb3, out_atoms, n_atoms);

    state_kernel<<<1, 64>>>(state, uw1, ub1, uw2, ub2, uw3, ub3,
                            out_state, n_bonds, n_atoms);
}

// round 17
// speedup vs baseline: 1.9597x; 1.1417x over previous
#include <cuda_runtime.h>
#include <cuda_fp16.h>
#include <math.h>
#include <stdint.h>

// ================= scratch (no allocations allowed) =================
#define MAX_ATOMS 100000
__device__ float g_b2a[MAX_ATOMS * 32];
__device__ float g_cnt[MAX_ATOMS];
__device__ float g_bsum[32];
__device__ float g_asum[32];
__device__ float g_eb1f[64];   // fused bias: eb1 + state @ ew1[96:128]
__device__ float g_vb1f[64];   // fused bias: vb1 + state @ vw1[64:96]
// pre-converted fp16 image of the atoms table (L2-resident, built once)
__device__ __align__(16) __half g_ath[MAX_ATOMS * 32];

// pre-transposed fp16 weight images Wt[n][k], padded k-stride
__device__ __align__(16) __half g_we[13568];  // W1(64x104)@0 W2(64x72)@6656 W3(32x72)@11264
__device__ __align__(16) __half g_wv[11520];  // V1(64x72)@0  V2(64x72)@4608 V3(32x72)@9216

__device__ __forceinline__ float selu_f(float x) {
    const float lam = 1.0507009873554805f;
    const float la  = 1.7580993408473766f;
    float e = __expf(x);
    return x > 0.f ? lam * x : fmaf(la, e, -la);
}

// fp32 pair -> fp16x2 word
__device__ __forceinline__ uint32_t pack_hi(float v0, float v1) {
    __half2 hp = __floats2half2_rn(v0, v1);
    return *(uint32_t*)&hp;
}

__device__ __forceinline__ uint32_t smem_u32(const void* p) {
    uint32_t a;
    asm("{ .reg .u64 t; cvta.to.shared.u64 t, %1; cvt.u32.u64 %0, t; }" : "=r"(a) : "l"(p));
    return a;
}

// ---- baseline-ISA ops (valid on plain sm_100) ----
__device__ __forceinline__ void ldmx4(uint32_t r[4], uint32_t addr) {
    asm volatile("ldmatrix.sync.aligned.m8n8.x4.shared.b16 {%0,%1,%2,%3}, [%4];"
        : "=r"(r[0]), "=r"(r[1]), "=r"(r[2]), "=r"(r[3]) : "r"(addr));
}
__device__ __forceinline__ void mma_f16(float c[4], const uint32_t a[4], uint32_t b0, uint32_t b1) {
    asm("mma.sync.aligned.m16n8k16.row.col.f32.f16.f16.f32 "
        "{%0,%1,%2,%3}, {%4,%5,%6,%7}, {%8,%9}, {%0,%1,%2,%3};"
        : "+f"(c[0]), "+f"(c[1]), "+f"(c[2]), "+f"(c[3])
        : "r"(a[0]), "r"(a[1]), "r"(a[2]), "r"(a[3]), "r"(b0), "r"(b1));
}
__device__ __forceinline__ void cp16(uint32_t dst, const void* src) {
    asm volatile("cp.async.ca.shared.global [%0], [%1], 16;" :: "r"(dst), "l"(src));
}
#define CP_COMMIT() asm volatile("cp.async.commit_group;" ::: "memory")
#define CP_WAIT0()  asm volatile("cp.async.wait_group 0;" ::: "memory")
// pair-scoped barrier: 2 warps (64 threads), ids 1..4
#define PAIR_BAR(wm) asm volatile("bar.sync %0, 64;" :: "r"((wm) + 1) : "memory")

// dense layer: acc[NTW][4] += A(16 rows x K) @ Wt^T  (fp16 single-pass)
template <int KS, int NTW>
__device__ __forceinline__ void mlp_layer(
    uint32_t x_addr, uint32_t b_addr, uint32_t sbwB,
    float acc[NTW][4])
{
#pragma unroll
    for (int j = 0; j < NTW; j++)
#pragma unroll
        for (int q = 0; q < 4; q++) acc[j][q] = 0.f;

#pragma unroll
    for (int k = 0; k < KS; k++) {
        uint32_t ah[4];
        ldmx4(ah, x_addr);
        x_addr += 32;
#pragma unroll
        for (int p = 0; p < NTW / 2; p++) {
            uint32_t rw[4];
            ldmx4(rw, b_addr + p * 8 * sbwB * 2);
            mma_f16(acc[2 * p],     ah, rw[0], rw[1]);
            mma_f16(acc[2 * p + 1], ah, rw[2], rw[3]);
        }
        b_addr += 32;
    }
}

// epilogue: bias+selu -> fp16 pair-LOCAL H image (rows 0..15, stride 36 words)
template <int NTW>
__device__ __forceinline__ void epi_to_h_hi(
    float acc[NTW][4], const float* bias,
    uint32_t* Hh, int wn, int g, int t)
{
    const int r0 = g;  // local row within pair
#pragma unroll
    for (int j = 0; j < NTW; j++) {
        int col = wn * 32 + j * 8 + 2 * t;
        int cw  = wn * 16 + j * 4 + t;
        float b0 = bias[col], b1 = bias[col + 1];
        Hh[r0 * 36 + cw]       = pack_hi(selu_f(acc[j][0] + b0), selu_f(acc[j][1] + b1));
        Hh[(r0 + 8) * 36 + cw] = pack_hi(selu_f(acc[j][2] + b0), selu_f(acc[j][3] + b1));
    }
}

// epilogue: bias+selu -> fp32 H3 [64][36] (global rows), N=32
__device__ __forceinline__ void epi_to_f32(
    float acc[2][4], const float* bias, float* H3, int wm, int wn, int g, int t)
{
    const int r0 = wm * 16 + g;
#pragma unroll
    for (int j = 0; j < 2; j++) {
        int col = wn * 16 + j * 8 + 2 * t;
        float b0 = bias[col], b1 = bias[col + 1];
        float2 v;
        v.x = selu_f(acc[j][0] + b0);
        v.y = selu_f(acc[j][1] + b1);
        *(float2*)&H3[r0 * 36 + col] = v;
        v.x = selu_f(acc[j][2] + b0);
        v.y = selu_f(acc[j][3] + b1);
        *(float2*)&H3[(r0 + 8) * 36 + col] = v;
    }
}

// ================= zero scratch + atoms fp16 convert =================
__global__ void zero_kernel(const float* __restrict__ atoms, int n_atoms)
{
    int i = blockIdx.x * blockDim.x + threadIdx.x;
    int stride = gridDim.x * blockDim.x;
    int nb = n_atoms * 32;
    for (int idx = i; idx < nb; idx += stride) {
        g_b2a[idx] = 0.f;
        g_ath[idx] = __float2half(atoms[idx]);
    }
    for (int idx = i; idx < n_atoms; idx += stride) g_cnt[idx] = 0.f;
    if (i < 32) { g_bsum[i] = 0.f; g_asum[i] = 0.f; }
}

// ================= weight transpose prep + state-bias fold =================
__global__ void prep_kernel(
    const float* __restrict__ ew1, const float* __restrict__ ew2, const float* __restrict__ ew3,
    const float* __restrict__ vw1, const float* __restrict__ vw2, const float* __restrict__ vw3,
    const float* __restrict__ eb1, const float* __restrict__ vb1,
    const float* __restrict__ state)
{
    int i = blockIdx.x * blockDim.x + threadIdx.x;
    if (i < 25088) {
        const float* src; __half* img;
        int stride, N, Ksrc, local;
        if (i < 6656)        { local = i;         stride = 104; N = 64; Ksrc = 96; src = ew1; img = g_we; }
        else if (i < 11264)  { local = i - 6656;  stride = 72;  N = 64; Ksrc = 64; src = ew2; img = g_we + 6656; }
        else if (i < 13568)  { local = i - 11264; stride = 72;  N = 32; Ksrc = 64; src = ew3; img = g_we + 11264; }
        else if (i < 18176)  { local = i - 13568; stride = 72;  N = 64; Ksrc = 64; src = vw1; img = g_wv; }
        else if (i < 22784)  { local = i - 18176; stride = 72;  N = 64; Ksrc = 64; src = vw2; img = g_wv + 4608; }
        else                 { local = i - 22784; stride = 72;  N = 32; Ksrc = 64; src = vw3; img = g_wv + 9216; }
        int n = local / stride, k = local % stride;
        float w = (k < Ksrc) ? src[k * N + n] : 0.f;
        img[local] = __float2half(w);
    } else if (i < 25216) {
        int n = i - 25088;
        if (n < 64) {
            float a = eb1[n];
            for (int j = 0; j < 32; j++) a = fmaf(state[j], ew1[(96 + j) * 64 + n], a);
            g_eb1f[n] = a;
        } else {
            n -= 64;
            float a = vb1[n];
            for (int j = 0; j < 32; j++) a = fmaf(state[j], vw1[(64 + j) * 64 + n], a);
            g_vb1f[n] = a;
        }
    }
}

// ================= smem maps (bytes) =================
// bond: Xh 13312 (K=96, stride 208B); pair H overlays own Xh range (832w >= 576w)
// H3 @ B_XB+13312 (9216); weights @ B_XB+22528: W1 13312, W2 @+13312, W3 @+22528
#define B_BIAS   0
#define B_A1S    640
#define B_XB     1024
#define B_WB     23552
#define B_SMEM   50688
// atom: Xh 9216 (K=64, stride 144B); pair H = pair Xh exactly (576w)
// H3 @ A_XB+9216 (9216); weights @ A_XB+18432: V1 9216, V2 @+9216, V3 @+18432
#define A_BIAS   0
#define A_XB     768
#define A_WB     19200
#define A_SMEM   42240

#define NT 256
#define TMROWS 64

// ================= phi_e over bonds =================
__global__ void __launch_bounds__(NT, 3) bond_kernel(
    const float* __restrict__ bonds, const int* __restrict__ ba1,
    const int* __restrict__ ba2,
    const float* __restrict__ eb2, const float* __restrict__ eb3,
    float* __restrict__ out_bonds, int n_bonds)
{
    extern __shared__ char smem[];
    const uint32_t sb = smem_u32(smem);
    const int tid  = threadIdx.x;
    const int wid  = tid >> 5;
    const int lane = tid & 31;
    const int g = lane >> 2, t = lane & 3;
    const int wm = wid >> 1, wn = wid & 1;   // 4 pairs x 2 n-warps
    const int base = blockIdx.x * TMROWS;

    float* Bs  = (float*)(smem + B_BIAS);
    int*   A1s = (int*)(smem + B_A1S);
    uint32_t* Xh = (uint32_t*)(smem + B_XB);
    // pair-local H (inside own Xh range: 832 words/pair >= 576 needed)
    uint32_t* Hh = Xh + wm * 832;
    float*    H3 = (float*)(smem + B_XB + 13312);

    // weights -> smem (cp.async), 27136 B
    for (int i = tid; i < 27136 / 16; i += NT)
        cp16(sb + B_WB + i * 16, (const char*)g_we + i * 16);
    CP_COMMIT();
    if (tid < 64) { Bs[tid] = g_eb1f[tid]; Bs[64 + tid] = eb2[tid]; }
    else if (tid < 96) Bs[128 + tid - 64] = eb3[tid - 64];

    // ---- stage X: 64 rows x 3 segments (a1 | a2 | bond), quarter 3 idle ----
    {
        const int m = tid >> 2, q = tid & 3;
        if (q < 3) {
            const int gid = base + m;
            const int wbase = m * 52 + q * 16;
            if (q < 2) {
                int a = (q == 0) ? ba1[gid] : ba2[gid];
                if (q == 0) { A1s[m] = a; atomicAdd(&g_cnt[a], 1.0f); }
                const int4* sh = (const int4*)(g_ath + (size_t)a * 32);
#pragma unroll
                for (int p = 0; p < 4; p++)
                    ((int4*)(Xh + wbase))[p] = sh[p];
            } else {
                const float* src = bonds + (size_t)gid * 32;
#pragma unroll
                for (int p = 0; p < 8; p++) {
                    float4 v = *(const float4*)(src + 4 * p);
                    Xh[wbase + 2 * p]     = pack_hi(v.x, v.y);
                    Xh[wbase + 2 * p + 1] = pack_hi(v.z, v.w);
                }
            }
        }
    }
    CP_WAIT0();
    __syncthreads();

    // lane-resolved fragment offsets
    const uint32_t a_loc = (uint32_t)(lane & 15);          // local row in pair
    const uint32_t a_kb  = (uint32_t)((lane >> 4) << 4);
    const uint32_t b_row = (uint32_t)(((lane >> 4) << 3) + (lane & 7));
    const uint32_t b_kb  = (uint32_t)(((lane >> 3) & 1) << 4);
    const uint32_t hb_h  = sb + B_XB + (uint32_t)wm * 3328;  // pair H base

    // ---- layer 1: K=96 (X stride 208B), W1 stride 208B ----
    {
        float acc[4][4];
        uint32_t ao = ((uint32_t)(wm * 16) + a_loc) * 208 + a_kb;
        uint32_t bo = (wn * 32 + b_row) * 208 + b_kb;
        mlp_layer<6, 4>(sb + B_XB + ao, sb + B_WB + bo, 208, acc);
        PAIR_BAR(wm);  // pair done reading its X rows
        epi_to_h_hi<4>(acc, Bs, Hh, wn, g, t);
    }
    PAIR_BAR(wm);

    // ---- layer 2: K=64 (H stride 144B), W2 stride 144B ----
    {
        float acc[4][4];
        uint32_t ao = a_loc * 144 + a_kb;
        uint32_t bo = (wn * 32 + b_row) * 144 + b_kb;
        mlp_layer<4, 4>(hb_h + ao, sb + B_WB + 13312 + bo, 144, acc);
        PAIR_BAR(wm);  // pair done reading H1
        epi_to_h_hi<4>(acc, Bs + 64, Hh, wn, g, t);
    }
    PAIR_BAR(wm);

    // ---- layer 3: K=64, N=32 ----
    {
        float acc[2][4];
        uint32_t ao = a_loc * 144 + a_kb;
        uint32_t bo = (wn * 16 + b_row) * 144 + b_kb;
        mlp_layer<4, 2>(hb_h + ao, sb + B_WB + 22528 + bo, 144, acc);
        epi_to_f32(acc, Bs + 128, H3, wm, wn, g, t);
    }
    __syncthreads();

    // ---- outputs ----
    for (int idx = tid; idx < TMROWS * 8; idx += NT) {
        int r = idx >> 3, f4 = idx & 7;
        float4 v = *(float4*)&H3[r * 36 + (f4 << 2)];
        *(float4*)&out_bonds[(size_t)(base + r) * 32 + (f4 << 2)] = v;
    }
    for (int r = wid; r < TMROWS; r += 8)
        atomicAdd(&g_b2a[(size_t)A1s[r] * 32 + lane], H3[r * 36 + lane]);
    if (tid < 32) {
        float ssum = 0.f;
        for (int r = 0; r < TMROWS; r++) ssum += H3[r * 36 + tid];
        atomicAdd(&g_bsum[tid], ssum);
    }
}

// ================= phi_v over atoms =================
__global__ void __launch_bounds__(NT, 3) atom_kernel(
    const float* __restrict__ vb2, const float* __restrict__ vb3,
    float* __restrict__ out_atoms, int n_atoms)
{
    extern __shared__ char smem[];
    const uint32_t sb = smem_u32(smem);
    const int tid  = threadIdx.x;
    const int wid  = tid >> 5;
    const int lane = tid & 31;
    const int g = lane >> 2, t = lane & 3;
    const int wm = wid >> 1, wn = wid & 1;
    const int base = blockIdx.x * TMROWS;

    float* Bs = (float*)(smem + A_BIAS);
    uint32_t* Xh = (uint32_t*)(smem + A_XB);
    uint32_t* Hh = Xh + wm * 576;   // pair X range = 16*36 = 576 words (exact H fit)
    float*    H3 = (float*)(smem + A_XB + 9216);

    for (int i = tid; i < 23040 / 16; i += NT)
        cp16(sb + A_WB + i * 16, (const char*)g_wv + i * 16);
    CP_COMMIT();
    if (tid < 64) { Bs[tid] = g_vb1f[tid]; Bs[64 + tid] = vb2[tid]; }
    else if (tid < 96) Bs[128 + tid - 64] = vb3[tid - 64];

    // ---- stage X: 64 rows x 2 segments (b2a | atoms); tid<128 active ----
    if (tid < 128) {
        const int m = tid >> 1, q = tid & 1;
        const int gm = base + m;
        const int id = gm < n_atoms ? gm : n_atoms - 1;
        const int wbase = m * 36 + q * 16;
        if (q == 0) {
            float inv = 1.0f / g_cnt[id];
#pragma unroll
            for (int p = 0; p < 8; p++) {
                float4 v = *(const float4*)&g_b2a[(size_t)id * 32 + 4 * p];
                Xh[wbase + 2 * p]     = pack_hi(v.x * inv, v.y * inv);
                Xh[wbase + 2 * p + 1] = pack_hi(v.z * inv, v.w * inv);
            }
        } else {
            const int4* sh = (const int4*)(g_ath + (size_t)id * 32);
#pragma unroll
            for (int p = 0; p < 4; p++)
                ((int4*)(Xh + wbase))[p] = sh[p];
        }
    }
    CP_WAIT0();
    __syncthreads();

    const uint32_t a_loc = (uint32_t)(lane & 15);
    const uint32_t a_kb  = (uint32_t)((lane >> 4) << 4);
    const uint32_t b_row = (uint32_t)(((lane >> 4) << 3) + (lane & 7));
    const uint32_t b_kb  = (uint32_t)(((lane >> 3) & 1) << 4);
    const uint32_t hb_h  = sb + A_XB + (uint32_t)wm * 2304;

    // ---- layer 1: K=64 (X stride 144B), V1 stride 144B ----
    {
        float acc[4][4];
        uint32_t ao = ((uint32_t)(wm * 16) + a_loc) * 144 + a_kb;
        uint32_t bo = (wn * 32 + b_row) * 144 + b_kb;
        mlp_layer<4, 4>(sb + A_XB + ao, sb + A_WB + bo, 144, acc);
        PAIR_BAR(wm);
        epi_to_h_hi<4>(acc, Bs, Hh, wn, g, t);
    }
    PAIR_BAR(wm);

    // ---- layer 2 ----
    {
        float acc[4][4];
        uint32_t ao = a_loc * 144 + a_kb;
        uint32_t bo = (wn * 32 + b_row) * 144 + b_kb;
        mlp_layer<4, 4>(hb_h + ao, sb + A_WB + 9216 + bo, 144, acc);
        PAIR_BAR(wm);
        epi_to_h_hi<4>(acc, Bs + 64, Hh, wn, g, t);
    }
    PAIR_BAR(wm);

    // ---- layer 3 ----
    {
        float acc[2][4];
        uint32_t ao = a_loc * 144 + a_kb;
        uint32_t bo = (wn * 16 + b_row) * 144 + b_kb;
        mlp_layer<4, 2>(hb_h + ao, sb + A_WB + 18432 + bo, 144, acc);
        epi_to_f32(acc, Bs + 128, H3, wm, wn, g, t);
    }
    __syncthreads();

    for (int idx = tid; idx < TMROWS * 8; idx += NT) {
        int r = idx >> 3, f4 = idx & 7;
        if (base + r < n_atoms) {
            float4 v = *(float4*)&H3[r * 36 + (f4 << 2)];
            *(float4*)&out_atoms[(size_t)(base + r) * 32 + (f4 << 2)] = v;
        }
    }
    if (tid < 32) {
        float ssum = 0.f;
        for (int r = 0; r < TMROWS; r++)
            if (base + r < n_atoms) ssum += H3[r * 36 + tid];
        atomicAdd(&g_asum[tid], ssum);
    }
}

// ================= phi_u =================
__global__ void state_kernel(
    const float* __restrict__ state,
    const float* __restrict__ uw1, const float* __restrict__ ub1,
    const float* __restrict__ uw2, const float* __restrict__ ub2,
    const float* __restrict__ uw3, const float* __restrict__ ub3,
    float* __restrict__ out_state, int n_bonds, int n_atoms)
{
    __shared__ float x[96], h1[64], h2[64];
    int tid = threadIdx.x;  // 64 threads
    if (tid < 32) {
        x[tid]      = g_bsum[tid] / (float)n_bonds;
        x[32 + tid] = g_asum[tid] / (float)n_atoms;
        x[64 + tid] = state[tid];
    }
    __syncthreads();
    {
        float a = ub1[tid];
        for (int k = 0; k < 96; k++) a = fmaf(x[k], uw1[k * 64 + tid], a);
        h1[tid] = selu_f(a);
    }
    __syncthreads();
    {
        float a = ub2[tid];
        for (int k = 0; k < 64; k++) a = fmaf(h1[k], uw2[k * 64 + tid], a);
        h2[tid] = selu_f(a);
    }
    __syncthreads();
    if (tid < 32) {
        float a = ub3[tid];
        for (int k = 0; k < 64; k++) a = fmaf(h2[k], uw3[k * 32 + tid], a);
        out_state[tid] = selu_f(a);
    }
}

// ================= launch =================
extern "C" void kernel_launch(void* const* d_in, const int* in_sizes, int n_in,
                              void* d_out, int out_size)
{
    const float* bonds = (const float*)d_in[0];
    const int*   ba1   = (const int*)d_in[1];
    const int*   ba2   = (const int*)d_in[2];
    const float* atoms = (const float*)d_in[3];
    const float* state = (const float*)d_in[4];
    const float* ew1 = (const float*)d_in[5];
    const float* eb1 = (const float*)d_in[6];
    const float* ew2 = (const float*)d_in[7];
    const float* eb2 = (const float*)d_in[8];
    const float* ew3 = (const float*)d_in[9];
    const float* eb3 = (const float*)d_in[10];
    const float* vw1 = (const float*)d_in[11];
    const float* vb1 = (const float*)d_in[12];
    const float* vw2 = (const float*)d_in[13];
    const float* vb2 = (const float*)d_in[14];
    const float* vw3 = (const float*)d_in[15];
    const float* vb3 = (const float*)d_in[16];
    const float* uw1 = (const float*)d_in[17];
    const float* ub1 = (const float*)d_in[18];
    const float* uw2 = (const float*)d_in[19];
    const float* ub2 = (const float*)d_in[20];
    const float* uw3 = (const float*)d_in[21];
    const float* ub3 = (const float*)d_in[22];

    const int n_bonds = in_sizes[1];
    const int n_atoms = in_sizes[3] / 32;

    float* out       = (float*)d_out;
    float* out_bonds = out;
    float* out_atoms = out + (size_t)n_bonds * 32;
    float* out_state = out_atoms + (size_t)n_atoms * 32;

    cudaFuncSetAttribute(bond_kernel, cudaFuncAttributeMaxDynamicSharedMemorySize, B_SMEM);
    cudaFuncSetAttribute(atom_kernel, cudaFuncAttributeMaxDynamicSharedMemorySize, A_SMEM);

    zero_kernel<<<256, 256>>>(atoms, n_atoms);
    prep_kernel<<<(25216 + 255) / 256, 256>>>(ew1, ew2, ew3, vw1, vw2, vw3,
                                              eb1, vb1, state);

    int bond_blocks = n_bonds / TMROWS;
    bond_kernel<<<bond_blocks, NT, B_SMEM>>>(
        bonds, ba1, ba2, eb2, eb3, out_bonds, n_bonds);

    int atom_blocks = (n_atoms + TMROWS - 1) / TMROWS;
    atom_kernel<<<atom_blocks, NT, A_SMEM>>>(
        vb2, vb3, out_atoms, n_atoms);

    state_kernel<<<1, 64>>>(state, uw1, ub1, uw2, ub2, uw3, ub3,
                            out_state, n_bonds, n_atoms);
}